// round 2
// baseline (speedup 1.0000x reference)
#include <cuda_runtime.h>

// ---------------------------------------------------------------------------
// VectorQuantizer (VQ-VAE) for GB300:
//   inputs [32, 256, 64, 64] f32, embedding [1024, 256] f32, beta scalar
//   out    = [loss][quantized tensor 32*256*64*64]  (loss first if out_size
//            has one extra element; tensor only otherwise)
//
// Pipeline:
//   prep_kernel     : ||e_k||^2 for all 1024 codes
//   argmin_kernel   : fused GEMM (f32x2 packed FFMA) + argmin with the
//                     reference's exact fp32 rounding:  s = fma(-2, x.e, Sx+Se)
//   gather_kernel   : quantized output + per-block partial MSE sums
//   finalize_kernel : deterministic loss reduction, loss = (1+beta)*MSE
// ---------------------------------------------------------------------------

#define B_    32
#define D_    256
#define HW_   4096
#define K_    1024
#define NROWS (B_ * HW_)               // 131072
#define TENSOR_ELEMS (B_ * D_ * HW_)   // 33554432

#define BN 128   // columns (hw) per block
#define BM 128   // codes per k-tile
#define DC 64    // d-chunk for E staging

#define XS_STRIDE 132   // 128 + 4 pad, multiple of 4 (float4-aligned rows)
#define ES_STRIDE 68    // 64 + 4 pad   (k-major E tile rows)

// smem (floats): Xs 256*132 | Es 128*68 | Ens 128 | Sxs 128
#define SMEM_FLOATS (256 * XS_STRIDE + BM * ES_STRIDE + 128 + 128)

__device__ float g_enorm[K_];
__device__ int   g_idx[NROWS];
__device__ float g_bsum[1024];

typedef unsigned long long ull;

__device__ __forceinline__ void fma2(ull& acc, ull a, ull b) {
    asm("fma.rn.f32x2 %0, %1, %2, %0;" : "+l"(acc) : "l"(a), "l"(b));
}
__device__ __forceinline__ ull pack2(float v) {
    ull r; unsigned u = __float_as_uint(v);
    asm("mov.b64 %0, {%1, %1};" : "=l"(r) : "r"(u));
    return r;
}
__device__ __forceinline__ void unpack2(ull p, float& lo, float& hi) {
    unsigned a, b;
    asm("mov.b64 {%0, %1}, %2;" : "=r"(a), "=r"(b) : "l"(p));
    lo = __uint_as_float(a); hi = __uint_as_float(b);
}

// ---------------- prep: ||e_k||^2 ------------------------------------------
__global__ void prep_kernel(const float* __restrict__ emb) {
    int k = blockIdx.x * blockDim.x + threadIdx.x;
    if (k < K_) {
        const float* r = emb + (size_t)k * D_;
        float s = 0.f;
        #pragma unroll 8
        for (int d = 0; d < D_; ++d) { float v = r[d]; s = fmaf(v, v, s); }
        g_enorm[k] = s;
    }
}

// ---------------- fused distance GEMM + argmin ------------------------------
__global__ __launch_bounds__(256, 1)
void argmin_kernel(const float* __restrict__ x, const float* __restrict__ emb) {
    extern __shared__ float sm[];
    float* Xs  = sm;                          // [256][XS_STRIDE]
    float* Es  = sm + 256 * XS_STRIDE;        // [BM][ES_STRIDE] (k-major)
    float* Ens = Es + BM * ES_STRIDE;         // [128] ||e||^2 for k-tile
    float* Sxs = Ens + 128;                   // [128] ||x||^2 per column

    const int tid = threadIdx.x;
    const int b   = blockIdx.y;
    const int c0  = blockIdx.x * BN;
    const float* xb = x + (size_t)b * (D_ * HW_) + c0;

    // Load X tile [256][128] (coalesced float4)
    for (int i = tid; i < (D_ * BN) / 4; i += 256) {
        int d = i >> 5, c4 = i & 31;
        float4 v = *(const float4*)(xb + (size_t)d * HW_ + c4 * 4);
        *(float4*)(Xs + d * XS_STRIDE + c4 * 4) = v;
    }
    __syncthreads();

    // ||x||^2 per column (conflict-free column walk)
    if (tid < BN) {
        float s = 0.f;
        #pragma unroll 8
        for (int d = 0; d < D_; ++d) {
            float v = Xs[d * XS_STRIDE + tid];
            s = fmaf(v, v, s);
        }
        Sxs[tid] = s;
    }
    // (consumed only after the staging __syncthreads below)

    const int tx = tid & 15, ty = tid >> 4;  // tx: col groups, ty: code groups
    float rmin[8]; int ridx[8];
    #pragma unroll
    for (int m = 0; m < 8; ++m) { rmin[m] = 3.4e38f; ridx[m] = 0; }

    for (int k0 = 0; k0 < K_; k0 += BM) {
        ull acc[8][4];
        #pragma unroll
        for (int i = 0; i < 8; ++i)
            #pragma unroll
            for (int j = 0; j < 4; ++j) acc[i][j] = 0ull;

        for (int d0 = 0; d0 < D_; d0 += DC) {
            __syncthreads();   // previous consumers of Es / Ens done
            // Stage E k-tile d-chunk, k-major rows (coalesced global loads)
            for (int i = tid; i < (BM * DC) / 4; i += 256) {
                int kk = i >> 4, dd4 = i & 15;
                float4 v = *(const float4*)(emb + (size_t)(k0 + kk) * D_ + d0 + dd4 * 4);
                *(float4*)(Es + kk * ES_STRIDE + dd4 * 4) = v;
            }
            if (d0 == 0 && tid < BM) Ens[tid] = g_enorm[k0 + tid];
            __syncthreads();

            #pragma unroll 8
            for (int dd = 0; dd < DC; ++dd) {
                // 8 code values (scalar LDS, warp-broadcast), packed {e,e}
                const float* eb = Es + (ty << 3) * ES_STRIDE + dd;
                ull ep[8];
                #pragma unroll
                for (int i = 0; i < 8; ++i) ep[i] = pack2(eb[i * ES_STRIDE]);
                // 8 columns = 4 f32x2 pairs (vector LDS)
                const ull* xr = (const ull*)(Xs + (d0 + dd) * XS_STRIDE + (tx << 3));
                ulonglong2 xv0 = *(const ulonglong2*)(xr);
                ulonglong2 xv1 = *(const ulonglong2*)(xr + 2);
                ull xp[4] = { xv0.x, xv0.y, xv1.x, xv1.y };
                #pragma unroll
                for (int i = 0; i < 8; ++i)
                    #pragma unroll
                    for (int j = 0; j < 4; ++j) fma2(acc[i][j], ep[i], xp[j]);
            }
        }

        // Epilogue: replicate reference rounding s = fl(fl(Sx+Se) - 2*dot)
        #pragma unroll
        for (int i = 0; i < 8; ++i) {
            int   code = k0 + (ty << 3) + i;
            float se   = Ens[(ty << 3) + i];
            #pragma unroll
            for (int j = 0; j < 4; ++j) {
                float lo, hi; unpack2(acc[i][j], lo, hi);
                int m0 = j * 2;
                float t0 = Sxs[(tx << 3) + m0]     + se;
                float t1 = Sxs[(tx << 3) + m0 + 1] + se;
                float s0 = fmaf(-2.f, lo, t0);
                float s1 = fmaf(-2.f, hi, t1);
                if (s0 < rmin[m0])     { rmin[m0]     = s0; ridx[m0]     = code; }
                if (s1 < rmin[m0 + 1]) { rmin[m0 + 1] = s1; ridx[m0 + 1] = code; }
            }
        }
    }

    __syncthreads();
    // Cross-thread (ty) reduction; reuse Xs region
    float* rv  = sm;                       // [16][BN]
    int*   riv = (int*)(sm + 16 * BN);     // [16][BN]
    #pragma unroll
    for (int m = 0; m < 8; ++m) {
        rv [ty * BN + (tx << 3) + m] = rmin[m];
        riv[ty * BN + (tx << 3) + m] = ridx[m];
    }
    __syncthreads();
    if (tid < BN) {
        float bv = rv[tid]; int bi = riv[tid];
        #pragma unroll
        for (int t = 1; t < 16; ++t) {
            float v  = rv [t * BN + tid];
            int   id = riv[t * BN + tid];
            if (v < bv || (v == bv && id < bi)) { bv = v; bi = id; }
        }
        g_idx[b * HW_ + c0 + tid] = bi;
    }
}

// ---------------- gather + output + partial loss ----------------------------
__global__ __launch_bounds__(256)
void gather_kernel(const float* __restrict__ x, const float* __restrict__ emb,
                   float* __restrict__ outT) {
    __shared__ int   sidx[128];
    __shared__ float ws[8];
    const int tid = threadIdx.x;
    const int b   = blockIdx.y;
    const int c0  = blockIdx.x * 128;
    if (tid < 128) sidx[tid] = g_idx[b * HW_ + c0 + tid];
    __syncthreads();

    const int c  = tid & 127;
    const int dh = tid >> 7;   // 0 or 1
    const float* er = emb + (size_t)sidx[c] * D_;
    size_t base = (size_t)b * (D_ * HW_) + c0 + c;

    float lsum = 0.f;
    #pragma unroll 4
    for (int d = dh; d < D_; d += 2) {
        float q  = er[d];
        size_t off = base + (size_t)d * HW_;
        float xv = x[off];
        float df = q - xv;
        lsum = fmaf(df, df, lsum);
        outT[off] = q;
    }
    #pragma unroll
    for (int o = 16; o; o >>= 1) lsum += __shfl_down_sync(0xffffffffu, lsum, o);
    if ((tid & 31) == 0) ws[tid >> 5] = lsum;
    __syncthreads();
    if (tid == 0) {
        float s = 0.f;
        #pragma unroll
        for (int i = 0; i < 8; ++i) s += ws[i];
        g_bsum[blockIdx.y * 32 + blockIdx.x] = s;   // deterministic (no atomics)
    }
}

// ---------------- loss finalize --------------------------------------------
__global__ void finalize_kernel(const float* beta, float* out) {
    __shared__ float sh[256];
    int tid = threadIdx.x;
    float s = 0.f;
    for (int i = tid; i < 1024; i += 256) s += g_bsum[i];
    sh[tid] = s; __syncthreads();
    for (int o = 128; o; o >>= 1) {
        if (tid < o) sh[tid] += sh[tid + o];
        __syncthreads();
    }
    if (tid == 0) {
        float bv = 0.25f;
        if (beta) {
            float f = *beta;
            if (f > 0.0f && f < 100.0f) {
                bv = f;
            } else {
                // dtype fallback: scalar may have been provided as float64
                double dv = *(const double*)beta;
                if (dv > 0.0 && dv < 100.0) bv = (float)dv;
            }
        }
        out[0] = (1.0f + bv) * (sh[0] / 33554432.0f);
    }
}

// ---------------------------------------------------------------------------
extern "C" void kernel_launch(void* const* d_in, const int* in_sizes, int n_in,
                              void* d_out, int out_size) {
    (void)in_sizes;
    const float* x    = (const float*)d_in[0];
    const float* emb  = (const float*)d_in[1];
    const float* beta = (n_in > 2) ? (const float*)d_in[2] : nullptr;
    float* out = (float*)d_out;

    int off = out_size - TENSOR_ELEMS;
    if (off < 0) off = 0;   // tuple flattens as (loss, tensor): loss first

    const int smem_bytes = SMEM_FLOATS * (int)sizeof(float);   // ~171 KB
    cudaFuncSetAttribute(argmin_kernel,
                         cudaFuncAttributeMaxDynamicSharedMemorySize, smem_bytes);

    prep_kernel<<<4, 256>>>(emb);
    argmin_kernel<<<dim3(HW_ / BN, B_), 256, smem_bytes>>>(x, emb);
    gather_kernel<<<dim3(HW_ / 128, B_), 256>>>(x, emb, out + off);
    if (off >= 1) finalize_kernel<<<1, 256>>>(beta, out);
}

// round 3
// speedup vs baseline: 1.0538x; 1.0538x over previous
#include <cuda_runtime.h>

// ---------------------------------------------------------------------------
// VectorQuantizer (VQ-VAE) for GB300:
//   inputs [32, 256, 64, 64] f32, embedding [1024, 256] f32, beta scalar
//   out    = [loss][quantized tensor 32*256*64*64]  (loss first if out_size
//            has one extra element; tensor only otherwise)
//
// Pipeline:
//   prep_kernel     : ||e_k||^2 for all 1024 codes
//   argmin_kernel   : fused GEMM (f32x2 packed FFMA) + argmin with the
//                     reference's exact fp32 rounding:  s = fma(-2, x.e, Sx+Se)
//   gather_kernel   : quantized output + per-block partial MSE sums
//   finalize_kernel : deterministic loss reduction, loss = (1+beta)*MSE
// ---------------------------------------------------------------------------

#define B_    32
#define D_    256
#define HW_   4096
#define K_    1024
#define NROWS (B_ * HW_)               // 131072
#define TENSOR_ELEMS (B_ * D_ * HW_)   // 33554432

#define BN 128   // columns (hw) per block
#define BM 128   // codes per k-tile
#define DC 64    // d-chunk for E staging

#define XS_STRIDE 132   // 128 + 4 pad, multiple of 4 (float4-aligned rows)
#define ES_STRIDE 68    // 64 + 4 pad   (k-major E tile rows)

// smem (floats): Xs 256*132 | Es 128*68 | Ens 128 | Sxs 128
#define SMEM_FLOATS (256 * XS_STRIDE + BM * ES_STRIDE + 128 + 128)

__device__ float g_enorm[K_];
__device__ int   g_idx[NROWS];
__device__ float g_bsum[1024];

typedef unsigned long long ull;

__device__ __forceinline__ void fma2(ull& acc, ull a, ull b) {
    asm("fma.rn.f32x2 %0, %1, %2, %0;" : "+l"(acc) : "l"(a), "l"(b));
}
__device__ __forceinline__ ull pack2(float v) {
    ull r; unsigned u = __float_as_uint(v);
    asm("mov.b64 %0, {%1, %1};" : "=l"(r) : "r"(u));
    return r;
}
__device__ __forceinline__ void unpack2(ull p, float& lo, float& hi) {
    unsigned a, b;
    asm("mov.b64 {%0, %1}, %2;" : "=r"(a), "=r"(b) : "l"(p));
    lo = __uint_as_float(a); hi = __uint_as_float(b);
}

// ---------------- prep: ||e_k||^2 ------------------------------------------
__global__ void prep_kernel(const float* __restrict__ emb) {
    int k = blockIdx.x * blockDim.x + threadIdx.x;
    if (k < K_) {
        const float* r = emb + (size_t)k * D_;
        float s = 0.f;
        #pragma unroll 8
        for (int d = 0; d < D_; ++d) { float v = r[d]; s = fmaf(v, v, s); }
        g_enorm[k] = s;
    }
}

// ---------------- fused distance GEMM + argmin ------------------------------
__global__ __launch_bounds__(256, 1)
void argmin_kernel(const float* __restrict__ x, const float* __restrict__ emb) {
    extern __shared__ float sm[];
    float* Xs  = sm;                          // [256][XS_STRIDE]
    float* Es  = sm + 256 * XS_STRIDE;        // [BM][ES_STRIDE] (k-major)
    float* Ens = Es + BM * ES_STRIDE;         // [128] ||e||^2 for k-tile
    float* Sxs = Ens + 128;                   // [128] ||x||^2 per column

    const int tid = threadIdx.x;
    const int b   = blockIdx.y;
    const int c0  = blockIdx.x * BN;
    const float* xb = x + (size_t)b * (D_ * HW_) + c0;

    // Load X tile [256][128] (coalesced float4)
    for (int i = tid; i < (D_ * BN) / 4; i += 256) {
        int d = i >> 5, c4 = i & 31;
        float4 v = *(const float4*)(xb + (size_t)d * HW_ + c4 * 4);
        *(float4*)(Xs + d * XS_STRIDE + c4 * 4) = v;
    }
    __syncthreads();

    // ||x||^2 per column (conflict-free column walk)
    if (tid < BN) {
        float s = 0.f;
        #pragma unroll 8
        for (int d = 0; d < D_; ++d) {
            float v = Xs[d * XS_STRIDE + tid];
            s = fmaf(v, v, s);
        }
        Sxs[tid] = s;
    }
    // (consumed only after the staging __syncthreads below)

    const int tx = tid & 15, ty = tid >> 4;  // tx: col groups, ty: code groups
    float rmin[8]; int ridx[8];
    #pragma unroll
    for (int m = 0; m < 8; ++m) { rmin[m] = 3.4e38f; ridx[m] = 0; }

    for (int k0 = 0; k0 < K_; k0 += BM) {
        ull acc[8][4];
        #pragma unroll
        for (int i = 0; i < 8; ++i)
            #pragma unroll
            for (int j = 0; j < 4; ++j) acc[i][j] = 0ull;

        for (int d0 = 0; d0 < D_; d0 += DC) {
            __syncthreads();   // previous consumers of Es / Ens done
            // Stage E k-tile d-chunk, k-major rows (coalesced global loads)
            for (int i = tid; i < (BM * DC) / 4; i += 256) {
                int kk = i >> 4, dd4 = i & 15;
                float4 v = *(const float4*)(emb + (size_t)(k0 + kk) * D_ + d0 + dd4 * 4);
                *(float4*)(Es + kk * ES_STRIDE + dd4 * 4) = v;
            }
            if (d0 == 0 && tid < BM) Ens[tid] = g_enorm[k0 + tid];
            __syncthreads();

            #pragma unroll 8
            for (int dd = 0; dd < DC; ++dd) {
                // 8 code values (scalar LDS, warp-broadcast), packed {e,e}
                const float* eb = Es + (ty << 3) * ES_STRIDE + dd;
                ull ep[8];
                #pragma unroll
                for (int i = 0; i < 8; ++i) ep[i] = pack2(eb[i * ES_STRIDE]);
                // 8 columns = 4 f32x2 pairs (vector LDS)
                const ull* xr = (const ull*)(Xs + (d0 + dd) * XS_STRIDE + (tx << 3));
                ulonglong2 xv0 = *(const ulonglong2*)(xr);
                ulonglong2 xv1 = *(const ulonglong2*)(xr + 2);
                ull xp[4] = { xv0.x, xv0.y, xv1.x, xv1.y };
                #pragma unroll
                for (int i = 0; i < 8; ++i)
                    #pragma unroll
                    for (int j = 0; j < 4; ++j) fma2(acc[i][j], ep[i], xp[j]);
            }
        }

        // Epilogue: replicate reference rounding s = fl(fl(Sx+Se) - 2*dot)
        #pragma unroll
        for (int i = 0; i < 8; ++i) {
            int   code = k0 + (ty << 3) + i;
            float se   = Ens[(ty << 3) + i];
            #pragma unroll
            for (int j = 0; j < 4; ++j) {
                float lo, hi; unpack2(acc[i][j], lo, hi);
                int m0 = j * 2;
                float t0 = Sxs[(tx << 3) + m0]     + se;
                float t1 = Sxs[(tx << 3) + m0 + 1] + se;
                float s0 = fmaf(-2.f, lo, t0);
                float s1 = fmaf(-2.f, hi, t1);
                if (s0 < rmin[m0])     { rmin[m0]     = s0; ridx[m0]     = code; }
                if (s1 < rmin[m0 + 1]) { rmin[m0 + 1] = s1; ridx[m0 + 1] = code; }
            }
        }
    }

    __syncthreads();
    // Cross-thread (ty) reduction; reuse Xs region
    float* rv  = sm;                       // [16][BN]
    int*   riv = (int*)(sm + 16 * BN);     // [16][BN]
    #pragma unroll
    for (int m = 0; m < 8; ++m) {
        rv [ty * BN + (tx << 3) + m] = rmin[m];
        riv[ty * BN + (tx << 3) + m] = ridx[m];
    }
    __syncthreads();
    if (tid < BN) {
        float bv = rv[tid]; int bi = riv[tid];
        #pragma unroll
        for (int t = 1; t < 16; ++t) {
            float v  = rv [t * BN + tid];
            int   id = riv[t * BN + tid];
            if (v < bv || (v == bv && id < bi)) { bv = v; bi = id; }
        }
        g_idx[b * HW_ + c0 + tid] = bi;
    }
}

// ---------------- gather + output + partial loss ----------------------------
__global__ __launch_bounds__(256)
void gather_kernel(const float* __restrict__ x, const float* __restrict__ emb,
                   float* __restrict__ outT) {
    __shared__ int   sidx[128];
    __shared__ float ws[8];
    const int tid = threadIdx.x;
    const int b   = blockIdx.y;
    const int c0  = blockIdx.x * 128;
    if (tid < 128) sidx[tid] = g_idx[b * HW_ + c0 + tid];
    __syncthreads();

    const int c  = tid & 127;
    const int dh = tid >> 7;   // 0 or 1
    const float* er = emb + (size_t)sidx[c] * D_;
    size_t base = (size_t)b * (D_ * HW_) + c0 + c;

    float lsum = 0.f;
    #pragma unroll 4
    for (int d = dh; d < D_; d += 2) {
        float q  = er[d];
        size_t off = base + (size_t)d * HW_;
        float xv = x[off];
        float df = q - xv;
        lsum = fmaf(df, df, lsum);
        outT[off] = q;
    }
    #pragma unroll
    for (int o = 16; o; o >>= 1) lsum += __shfl_down_sync(0xffffffffu, lsum, o);
    if ((tid & 31) == 0) ws[tid >> 5] = lsum;
    __syncthreads();
    if (tid == 0) {
        float s = 0.f;
        #pragma unroll
        for (int i = 0; i < 8; ++i) s += ws[i];
        g_bsum[blockIdx.y * 32 + blockIdx.x] = s;   // deterministic (no atomics)
    }
}

// ---------------- loss finalize --------------------------------------------
__global__ void finalize_kernel(const float* beta, float* out) {
    __shared__ float sh[256];
    int tid = threadIdx.x;
    float s = 0.f;
    for (int i = tid; i < 1024; i += 256) s += g_bsum[i];
    sh[tid] = s; __syncthreads();
    for (int o = 128; o; o >>= 1) {
        if (tid < o) sh[tid] += sh[tid + o];
        __syncthreads();
    }
    if (tid == 0) {
        float bv = 0.25f;
        if (beta) {
            float f = *beta;
            if (f > 0.0f && f < 100.0f) {
                bv = f;
            } else {
                // dtype fallback: scalar may have been provided as float64
                double dv = *(const double*)beta;
                if (dv > 0.0 && dv < 100.0) bv = (float)dv;
            }
        }
        out[0] = (1.0f + bv) * (sh[0] / 33554432.0f);
    }
}

// ---------------------------------------------------------------------------
extern "C" void kernel_launch(void* const* d_in, const int* in_sizes, int n_in,
                              void* d_out, int out_size) {
    (void)in_sizes;
    const float* x    = (const float*)d_in[0];
    const float* emb  = (const float*)d_in[1];
    const float* beta = (n_in > 2) ? (const float*)d_in[2] : nullptr;
    float* out = (float*)d_out;

    int off = out_size - TENSOR_ELEMS;
    if (off < 0) off = 0;   // tuple flattens as (loss, tensor): loss first

    const int smem_bytes = SMEM_FLOATS * (int)sizeof(float);   // ~171 KB
    cudaFuncSetAttribute(argmin_kernel,
                         cudaFuncAttributeMaxDynamicSharedMemorySize, smem_bytes);

    prep_kernel<<<4, 256>>>(emb);
    argmin_kernel<<<dim3(HW_ / BN, B_), 256, smem_bytes>>>(x, emb);
    gather_kernel<<<dim3(HW_ / 128, B_), 256>>>(x, emb, out + off);
    if (off >= 1) finalize_kernel<<<1, 256>>>(beta, out);
}

// round 6
// speedup vs baseline: 1.9432x; 1.8439x over previous
#include <cuda_runtime.h>
#include <cuda_bf16.h>
#include <cstdint>

#define B_    32
#define D_    256
#define HW_   4096
#define K_    1024
#define NROWS (B_ * HW_)
#define TENSOR_ELEMS (B_ * D_ * HW_)
#define THRESH 1.0e-4f

__device__ __nv_bfloat16 g_ehi[K_ * D_];   // bf16 hi of (-2*E), k-major rows
__device__ __nv_bfloat16 g_elo[K_ * D_];   // bf16 residual of (-2*E)
__device__ float g_enorm[K_];
__device__ int   g_idx[NROWS];
__device__ float g_bsum[1024];
__device__ int   g_fixn;
__device__ int   g_fixlist[NROWS];

// ---------------- PTX helpers (all plain sm_80-level, no 'a' features) ------
__device__ __forceinline__ uint32_t smem_u32(const void* p) {
    uint32_t a;
    asm("{ .reg .u64 t; cvta.to.shared.u64 t, %1; cvt.u32.u64 %0, t; }" : "=r"(a) : "l"(p));
    return a;
}
__device__ __forceinline__ void cp16(uint32_t dst, const void* src) {
    asm volatile("cp.async.cg.shared.global [%0], [%1], 16;" :: "r"(dst), "l"(src) : "memory");
}
#define CP_COMMIT() asm volatile("cp.async.commit_group;" ::: "memory")
#define CP_WAIT0()  asm volatile("cp.async.wait_group 0;" ::: "memory")
#define CP_WAIT1()  asm volatile("cp.async.wait_group 1;" ::: "memory")

__device__ __forceinline__ void ldsm4(uint32_t* r, uint32_t addr) {
    asm volatile("ldmatrix.sync.aligned.m8n8.x4.shared.b16 {%0,%1,%2,%3}, [%4];"
                 : "=r"(r[0]), "=r"(r[1]), "=r"(r[2]), "=r"(r[3]) : "r"(addr));
}
__device__ __forceinline__ void ldsm2(uint32_t* r, uint32_t addr) {
    asm volatile("ldmatrix.sync.aligned.m8n8.x2.shared.b16 {%0,%1}, [%2];"
                 : "=r"(r[0]), "=r"(r[1]) : "r"(addr));
}
__device__ __forceinline__ void mma16816(float* c, const uint32_t* a, const uint32_t* b) {
    asm volatile("mma.sync.aligned.m16n8k16.row.col.f32.bf16.bf16.f32 "
                 "{%0,%1,%2,%3}, {%4,%5,%6,%7}, {%8,%9}, {%0,%1,%2,%3};"
                 : "+f"(c[0]), "+f"(c[1]), "+f"(c[2]), "+f"(c[3])
                 : "r"(a[0]), "r"(a[1]), "r"(a[2]), "r"(a[3]), "r"(b[0]), "r"(b[1]));
}

// smem layout (bytes)
#define SM_XHI   0
#define SM_XLO   65536
#define SM_E     131072      // [EHI0 16K][ELO0 16K][EHI1 16K][ELO1 16K]
#define SM_SE    196608      // 1024 f32
#define SM_SXP   200704      // 256 f32 (two halves of ||x||^2 per pixel)
#define SM_RED   201728      // 128 pixels x 4 warpN x 3 f32
#define SM_TOTAL 207872

// ---------------- prep: split (-2E) into bf16 hi/lo, ||e||^2 ----------------
__global__ void prep_kernel(const float* __restrict__ emb) {
    int k = blockIdx.x, d = threadIdx.x;
    float e2 = -2.0f * emb[k * D_ + d];
    __nv_bfloat16 h = __float2bfloat16(e2);
    __nv_bfloat16 l = __float2bfloat16(e2 - __bfloat162float(h));
    g_ehi[k * D_ + d] = h;
    g_elo[k * D_ + d] = l;
    if (d == 0) {
        const float* r = emb + (size_t)k * D_;
        float s = 0.f;
        for (int i = 0; i < D_; ++i) { float v = r[i]; s = fmaf(v, v, s); }
        g_enorm[k] = s;
        if (k == 0) g_fixn = 0;
    }
}

// ---------------- HMMA argmin ----------------------------------------------
__global__ __launch_bounds__(256, 1)
void argmin_kernel(const float* __restrict__ x) {
    extern __shared__ char smem[];
    const uint32_t sb = smem_u32(smem);
    float* sSe  = (float*)(smem + SM_SE);
    float* sSxp = (float*)(smem + SM_SXP);
    float* red  = (float*)(smem + SM_RED);

    const int tid  = threadIdx.x;
    const int lane = tid & 31;
    const int w    = tid >> 5;
    const int wm   = w & 1;        // pixel-half: 0 -> rows 0-63, 1 -> 64-127
    const int wn   = w >> 1;       // code group within pass (4 x 32 codes)
    const int b    = blockIdx.x >> 5;
    const int c0   = (blockIdx.x & 31) * 128;

    for (int i = tid; i < K_; i += 256) sSe[i] = g_enorm[i];

    // ---- prefetch E (pass0, chunk0) into buffer 0 while X stages
    {
        #pragma unroll
        for (int i = 0; i < 4; ++i) {
            int idx = tid + i * 256;
            int r = idx >> 3, s = idx & 7;
            uint32_t dst = (uint32_t)((r >> 3) * 1024 + (r & 7) * 128 +
                                      ((s * 16) ^ ((r & 7) << 4)));
            cp16(sb + SM_E + dst,         g_ehi + (size_t)r * D_ + s * 8);
            cp16(sb + SM_E + 16384 + dst, g_elo + (size_t)r * D_ + s * 8);
        }
        CP_COMMIT();
    }

    // ---- stage X tile [128 pixels x 256 d] bf16 hi/lo, SW128 K-major
    {
        const int p = tid & 127, half = tid >> 7;
        const float* xb = x + (size_t)b * (D_ * HW_) + c0 + p;
        const uint32_t rowbase = (uint32_t)((p >> 3) * 1024 + (p & 7) * 128);
        const uint32_t rx = (uint32_t)((p & 7) << 4);
        float Sx = 0.f;
        for (int d0 = half * 128; d0 < half * 128 + 128; d0 += 8) {
            float v[8];
            #pragma unroll
            for (int i = 0; i < 8; ++i) v[i] = xb[(size_t)(d0 + i) * HW_];
            #pragma unroll
            for (int i = 0; i < 8; ++i) Sx = fmaf(v[i], v[i], Sx);
            uint32_t hp[4], lp[4];
            #pragma unroll
            for (int i = 0; i < 4; ++i) {
                __nv_bfloat16 h0 = __float2bfloat16(v[2*i]);
                __nv_bfloat16 h1 = __float2bfloat16(v[2*i+1]);
                __nv_bfloat16 l0 = __float2bfloat16(v[2*i]   - __bfloat162float(h0));
                __nv_bfloat16 l1 = __float2bfloat16(v[2*i+1] - __bfloat162float(h1));
                hp[i] = (uint32_t)__bfloat16_as_ushort(h0) | ((uint32_t)__bfloat16_as_ushort(h1) << 16);
                lp[i] = (uint32_t)__bfloat16_as_ushort(l0) | ((uint32_t)__bfloat16_as_ushort(l1) << 16);
            }
            uint32_t off = (uint32_t)(d0 >> 6) * 16384u + rowbase +
                           (((uint32_t)(d0 & 63) * 2u) ^ rx);
            *(uint4*)(smem + SM_XHI + off) = make_uint4(hp[0], hp[1], hp[2], hp[3]);
            *(uint4*)(smem + SM_XLO + off) = make_uint4(lp[0], lp[1], lp[2], lp[3]);
        }
        sSxp[half * 128 + p] = Sx;
    }
    __syncthreads();

    // per-lane Sx for the 8 row-slots it owns
    float sx[8];
    #pragma unroll
    for (int s = 0; s < 8; ++s) {
        int pix = wm * 64 + (s >> 1) * 16 + (lane >> 2) + (s & 1) * 8;
        sx[s] = sSxp[pix] + sSxp[128 + pix];
    }

    // ldmatrix address constants
    uint32_t aOff[4], aXor[4], bOff[4], bXor[4];
    #pragma unroll
    for (int mt = 0; mt < 4; ++mt) {
        int r = wm * 64 + mt * 16 + (lane & 7) + ((lane >> 3) & 1) * 8;
        aOff[mt] = (uint32_t)((r >> 3) * 1024 + (r & 7) * 128);
        aXor[mt] = (uint32_t)((r & 7) << 4);
    }
    #pragma unroll
    for (int nt = 0; nt < 4; ++nt) {
        int n = wn * 32 + nt * 8 + (lane & 7);
        bOff[nt] = (uint32_t)((n >> 3) * 1024 + (n & 7) * 128);
        bXor[nt] = (uint32_t)((n & 7) << 4);
    }
    const uint32_t adB = (lane >> 4) ? 16u : 0u;          // A: k+8 half
    const uint32_t bdB = ((lane >> 3) & 1) ? 16u : 0u;    // B: k+8 half

    float m1r[8], m2r[8]; int i1r[8];
    #pragma unroll
    for (int s = 0; s < 8; ++s) { m1r[s] = 3.4e38f; m2r[s] = 3.4e38f; i1r[s] = 0; }

    float acc[4][4][4];

    for (int seg = 0; seg < 32; ++seg) {        // seg = pass*4 + chunk
        const int ch = seg & 3;
        // prefetch next segment's E chunk into the other buffer
        if (seg < 31) {
            const int np = (seg + 1) >> 2, nc = (seg + 1) & 3;
            const __nv_bfloat16* Eh = g_ehi + (size_t)np * 128 * D_ + nc * 64;
            const __nv_bfloat16* El = g_elo + (size_t)np * 128 * D_ + nc * 64;
            uint32_t ebase = sb + SM_E + (uint32_t)((seg + 1) & 1) * 32768u;
            #pragma unroll
            for (int i = 0; i < 4; ++i) {
                int idx = tid + i * 256;
                int r = idx >> 3, s = idx & 7;
                uint32_t dst = (uint32_t)((r >> 3) * 1024 + (r & 7) * 128 +
                                          ((s * 16) ^ ((r & 7) << 4)));
                cp16(ebase + dst,         Eh + (size_t)r * D_ + s * 8);
                cp16(ebase + 16384 + dst, El + (size_t)r * D_ + s * 8);
            }
            CP_COMMIT();
            CP_WAIT1();
        } else {
            CP_WAIT0();
        }
        __syncthreads();

        if (ch == 0) {
            #pragma unroll
            for (int mt = 0; mt < 4; ++mt)
                #pragma unroll
                for (int nt = 0; nt < 4; ++nt)
                    #pragma unroll
                    for (int q = 0; q < 4; ++q) acc[mt][nt][q] = 0.f;
        }

        const uint32_t eh = sb + SM_E + (uint32_t)(seg & 1) * 32768u;
        const uint32_t el = eh + 16384u;
        const uint32_t xco = (uint32_t)ch * 16384u;

        #pragma unroll
        for (int ks = 0; ks < 4; ++ks) {
            const uint32_t dA = (uint32_t)(ks * 32) + adB;
            const uint32_t dB = (uint32_t)(ks * 32) + bdB;
            uint32_t bh[4][2], bl[4][2], ah[4][4], al[4][4];
            #pragma unroll
            for (int nt = 0; nt < 4; ++nt) {
                ldsm2(bh[nt], eh + bOff[nt] + (dB ^ bXor[nt]));
                ldsm2(bl[nt], el + bOff[nt] + (dB ^ bXor[nt]));
            }
            #pragma unroll
            for (int mt = 0; mt < 4; ++mt) {
                ldsm4(ah[mt], sb + SM_XHI + xco + aOff[mt] + (dA ^ aXor[mt]));
                ldsm4(al[mt], sb + SM_XLO + xco + aOff[mt] + (dA ^ aXor[mt]));
            }
            #pragma unroll
            for (int mt = 0; mt < 4; ++mt)
                #pragma unroll
                for (int nt = 0; nt < 4; ++nt) {
                    mma16816(acc[mt][nt], ah[mt], bh[nt]);   // Xhi * Ehi
                    mma16816(acc[mt][nt], ah[mt], bl[nt]);   // Xhi * Elo
                    mma16816(acc[mt][nt], al[mt], bh[nt]);   // Xlo * Ehi
                }
        }

        if (ch == 3) {   // end of pass: fold scores into running top-2
            const int pass = seg >> 2;
            const int cbase = pass * 128 + wn * 32 + 2 * (lane & 3);
            #pragma unroll
            for (int nt = 0; nt < 4; ++nt) {
                const int code0 = cbase + nt * 8;
                const float se0 = sSe[code0], se1 = sSe[code0 + 1];
                #pragma unroll
                for (int mt = 0; mt < 4; ++mt) {
                    const int s0 = mt * 2, s1 = mt * 2 + 1;
                    float v;
                    v = sx[s0] + se0 + acc[mt][nt][0];
                    if (v < m1r[s0]) { m2r[s0] = m1r[s0]; m1r[s0] = v; i1r[s0] = code0; }
                    else if (v < m2r[s0]) m2r[s0] = v;
                    v = sx[s0] + se1 + acc[mt][nt][1];
                    if (v < m1r[s0]) { m2r[s0] = m1r[s0]; m1r[s0] = v; i1r[s0] = code0 + 1; }
                    else if (v < m2r[s0]) m2r[s0] = v;
                    v = sx[s1] + se0 + acc[mt][nt][2];
                    if (v < m1r[s1]) { m2r[s1] = m1r[s1]; m1r[s1] = v; i1r[s1] = code0; }
                    else if (v < m2r[s1]) m2r[s1] = v;
                    v = sx[s1] + se1 + acc[mt][nt][3];
                    if (v < m1r[s1]) { m2r[s1] = m1r[s1]; m1r[s1] = v; i1r[s1] = code0 + 1; }
                    else if (v < m2r[s1]) m2r[s1] = v;
                }
            }
        }
        __syncthreads();
    }

    // reduce across the 4 lanes of each quad (same rows, different cols)
    #pragma unroll
    for (int s = 0; s < 8; ++s) {
        float a1 = m1r[s], a2 = m2r[s]; int ai = i1r[s];
        #pragma unroll
        for (int ofs = 1; ofs <= 2; ofs <<= 1) {
            float v1 = __shfl_xor_sync(0xffffffffu, a1, ofs);
            float v2 = __shfl_xor_sync(0xffffffffu, a2, ofs);
            int   vi = __shfl_xor_sync(0xffffffffu, ai, ofs);
            if (v1 < a1 || (v1 == a1 && vi < ai)) { a2 = fminf(a1, v2); a1 = v1; ai = vi; }
            else                                  { a2 = fminf(a2, v1); }
        }
        if ((lane & 3) == 0) {
            int pix = wm * 64 + (s >> 1) * 16 + (lane >> 2) + (s & 1) * 8;
            red[(pix * 4 + wn) * 3 + 0] = a1;
            red[(pix * 4 + wn) * 3 + 1] = a2;
            red[(pix * 4 + wn) * 3 + 2] = __int_as_float(ai);
        }
    }
    __syncthreads();

    if (tid < 128) {
        float a1 = red[(tid * 4) * 3], a2 = red[(tid * 4) * 3 + 1];
        int   ai = __float_as_int(red[(tid * 4) * 3 + 2]);
        #pragma unroll
        for (int q = 1; q < 4; ++q) {
            float v1 = red[(tid * 4 + q) * 3], v2 = red[(tid * 4 + q) * 3 + 1];
            int   vi = __float_as_int(red[(tid * 4 + q) * 3 + 2]);
            if (v1 < a1 || (v1 == a1 && vi < ai)) { a2 = fminf(a1, v2); a1 = v1; ai = vi; }
            else                                  { a2 = fminf(a2, v1); }
        }
        const int row = b * HW_ + c0 + tid;
        g_idx[row] = ai;
        if (a2 - a1 < THRESH) {
            int pos = atomicAdd(&g_fixn, 1);
            g_fixlist[pos] = row;
        }
    }
}

// ---------------- exact-fp32 fixup of near-tie rows -------------------------
#define FX_SX   0
#define FX_ED   16448
#define FX_SSX  (FX_ED + 69632)
#define FX_ROWS (FX_SSX + 64)
#define FX_TOTAL (FX_ROWS + 64)

__global__ __launch_bounds__(256)
void fixup_kernel(const float* __restrict__ x, const float* __restrict__ emb) {
    extern __shared__ char fsm[];
    float* sx  = (float*)(fsm + FX_SX);    // [16][257]
    float* ed  = (float*)(fsm + FX_ED);    // [256][68] transposed codes
    float* sSx = (float*)(fsm + FX_SSX);
    int*   rws = (int*)(fsm + FX_ROWS);

    const int n = g_fixn;
    const int tid = threadIdx.x;
    const int r  = tid >> 4;
    const int tc = tid & 15;

    for (int base = blockIdx.x * 16; base < n; base += gridDim.x * 16) {
        if (tid < 16) rws[tid] = (base + tid < n) ? g_fixlist[base + tid] : -1;
        __syncthreads();
        for (int i = tid; i < 16 * D_; i += 256) {
            int rr = i >> 8, d = i & 255;
            int row = rws[rr];
            int row_c = (row < 0) ? 0 : row;
            int bb = row_c >> 12, pix = row_c & 4095;
            sx[rr * 257 + d] = x[(size_t)bb * (D_ * HW_) + (size_t)d * HW_ + pix];
        }
        __syncthreads();
        if (tc == 0) {
            float s = 0.f;
            for (int d = 0; d < D_; ++d) { float v = sx[r * 257 + d]; s = fmaf(v, v, s); }
            sSx[r] = s;
        }
        float m = 3.4e38f; int bi = 0;
        for (int cb = 0; cb < 16; ++cb) {
            __syncthreads();
            {
                int cc = tid >> 2, dseg = (tid & 3) * 64;
                const float* er = emb + (size_t)(cb * 64 + cc) * D_ + dseg;
                for (int i = 0; i < 64; i += 4) {
                    float4 v = *(const float4*)(er + i);
                    ed[(dseg + i)     * 68 + cc] = v.x;
                    ed[(dseg + i + 1) * 68 + cc] = v.y;
                    ed[(dseg + i + 2) * 68 + cc] = v.z;
                    ed[(dseg + i + 3) * 68 + cc] = v.w;
                }
            }
            __syncthreads();
            float a0 = 0.f, a1 = 0.f, a2 = 0.f, a3 = 0.f;
            const float* xr = sx + r * 257;
            for (int d = 0; d < D_; ++d) {
                float xv = xr[d];
                float4 ev = *(const float4*)(ed + d * 68 + tc * 4);
                a0 = fmaf(ev.x, xv, a0);
                a1 = fmaf(ev.y, xv, a1);
                a2 = fmaf(ev.z, xv, a2);
                a3 = fmaf(ev.w, xv, a3);
            }
            float accv[4] = {a0, a1, a2, a3};
            float Sxr = sSx[r];
            #pragma unroll
            for (int j = 0; j < 4; ++j) {
                int code = cb * 64 + tc * 4 + j;
                float s = fmaf(-2.f, accv[j], Sxr + g_enorm[code]);
                if (s < m) { m = s; bi = code; }
            }
        }
        #pragma unroll
        for (int off = 8; off; off >>= 1) {
            float ov = __shfl_down_sync(0xffffffffu, m, off, 16);
            int   oi = __shfl_down_sync(0xffffffffu, bi, off, 16);
            if (ov < m || (ov == m && oi < bi)) { m = ov; bi = oi; }
        }
        if (tc == 0 && rws[r] >= 0) g_idx[rws[r]] = bi;
        __syncthreads();
    }
}

// ---------------- gather + STE output + partial loss ------------------------
__global__ __launch_bounds__(256)
void gather_kernel(const float* __restrict__ x, const float* __restrict__ emb,
                   float* __restrict__ outT) {
    __shared__ int   sidx[128];
    __shared__ float ws[8];
    const int tid = threadIdx.x;
    const int b   = blockIdx.y;
    const int c0  = blockIdx.x * 128;
    if (tid < 128) sidx[tid] = g_idx[b * HW_ + c0 + tid];
    __syncthreads();

    const int c  = tid & 127;
    const int dh = tid >> 7;
    const float* er = emb + (size_t)sidx[c] * D_;
    size_t base = (size_t)b * (D_ * HW_) + c0 + c;

    float lsum = 0.f;
    #pragma unroll 4
    for (int d = dh; d < D_; d += 2) {
        float q  = er[d];
        size_t off = base + (size_t)d * HW_;
        float xv = x[off];
        float df = q - xv;
        lsum = fmaf(df, df, lsum);
        outT[off] = xv + df;          // STE: fl(x + fl(q - x))
    }
    #pragma unroll
    for (int o = 16; o; o >>= 1) lsum += __shfl_down_sync(0xffffffffu, lsum, o);
    if ((tid & 31) == 0) ws[tid >> 5] = lsum;
    __syncthreads();
    if (tid == 0) {
        float s = 0.f;
        #pragma unroll
        for (int i = 0; i < 8; ++i) s += ws[i];
        g_bsum[blockIdx.y * 32 + blockIdx.x] = s;
    }
}

// ---------------- loss finalize --------------------------------------------
__global__ void finalize_kernel(const float* beta, float* out) {
    __shared__ float sh[256];
    int tid = threadIdx.x;
    float s = 0.f;
    for (int i = tid; i < 1024; i += 256) s += g_bsum[i];
    sh[tid] = s; __syncthreads();
    for (int o = 128; o; o >>= 1) {
        if (tid < o) sh[tid] += sh[tid + o];
        __syncthreads();
    }
    if (tid == 0) {
        float bv = 0.25f;
        if (beta) {
            float f = *beta;
            if (f > 0.0f && f < 100.0f) bv = f;
            else {
                double dv = *(const double*)beta;
                if (dv > 0.0 && dv < 100.0) bv = (float)dv;
            }
        }
        out[0] = (1.0f + bv) * (sh[0] / 33554432.0f);
    }
}

// ---------------------------------------------------------------------------
extern "C" void kernel_launch(void* const* d_in, const int* in_sizes, int n_in,
                              void* d_out, int out_size) {
    (void)in_sizes;
    const float* x    = (const float*)d_in[0];
    const float* emb  = (const float*)d_in[1];
    const float* beta = (n_in > 2) ? (const float*)d_in[2] : nullptr;
    float* out = (float*)d_out;

    int off = out_size - TENSOR_ELEMS;
    if (off < 0) off = 0;

    cudaFuncSetAttribute(argmin_kernel,
                         cudaFuncAttributeMaxDynamicSharedMemorySize, SM_TOTAL);
    cudaFuncSetAttribute(fixup_kernel,
                         cudaFuncAttributeMaxDynamicSharedMemorySize, FX_TOTAL);

    prep_kernel<<<K_, 256>>>(emb);
    argmin_kernel<<<1024, 256, SM_TOTAL>>>(x);
    fixup_kernel<<<256, 256, FX_TOTAL>>>(x, emb);
    gather_kernel<<<dim3(32, 32), 256>>>(x, emb, out + off);
    if (off >= 1) finalize_kernel<<<1, 256>>>(beta, out);
}

// round 7
// speedup vs baseline: 2.2616x; 1.1638x over previous
#include <cuda_runtime.h>
#include <cuda_fp16.h>
#include <cstdint>

#define B_    32
#define D_    256
#define HW_   4096
#define K_    1024
#define NROWS (B_ * HW_)
#define TENSOR_ELEMS (B_ * D_ * HW_)
#define THRESH 2.5e-4f

__device__ __half g_eh[K_ * D_];     // fp16 of (-2*E), k-major rows
__device__ float g_enorm[K_];
__device__ int   g_idx[NROWS];
__device__ float g_bsum[1024];
__device__ int   g_fixn;
__device__ int   g_fixlist[NROWS];

// ---------------- PTX helpers (plain sm_80-level, no 'a' features) ----------
__device__ __forceinline__ uint32_t smem_u32(const void* p) {
    uint32_t a;
    asm("{ .reg .u64 t; cvta.to.shared.u64 t, %1; cvt.u32.u64 %0, t; }" : "=r"(a) : "l"(p));
    return a;
}
__device__ __forceinline__ void cp16(uint32_t dst, const void* src) {
    asm volatile("cp.async.cg.shared.global [%0], [%1], 16;" :: "r"(dst), "l"(src) : "memory");
}
#define CP_COMMIT() asm volatile("cp.async.commit_group;" ::: "memory")
#define CP_WAIT0()  asm volatile("cp.async.wait_group 0;" ::: "memory")
#define CP_WAIT1()  asm volatile("cp.async.wait_group 1;" ::: "memory")

__device__ __forceinline__ void ldsm4(uint32_t* r, uint32_t addr) {
    asm volatile("ldmatrix.sync.aligned.m8n8.x4.shared.b16 {%0,%1,%2,%3}, [%4];"
                 : "=r"(r[0]), "=r"(r[1]), "=r"(r[2]), "=r"(r[3]) : "r"(addr));
}
__device__ __forceinline__ void ldsm2(uint32_t* r, uint32_t addr) {
    asm volatile("ldmatrix.sync.aligned.m8n8.x2.shared.b16 {%0,%1}, [%2];"
                 : "=r"(r[0]), "=r"(r[1]) : "r"(addr));
}
__device__ __forceinline__ void mma16816(float* c, const uint32_t* a, const uint32_t* b) {
    asm volatile("mma.sync.aligned.m16n8k16.row.col.f32.f16.f16.f32 "
                 "{%0,%1,%2,%3}, {%4,%5,%6,%7}, {%8,%9}, {%0,%1,%2,%3};"
                 : "+f"(c[0]), "+f"(c[1]), "+f"(c[2]), "+f"(c[3])
                 : "r"(a[0]), "r"(a[1]), "r"(a[2]), "r"(a[3]), "r"(b[0]), "r"(b[1]));
}

// smem layout (bytes)
#define SM_XHI   0           // [128 pixels x 256 d] fp16, SW128 K-major: 64 KB
#define SM_E     65536       // double buffer: 2 x 16 KB
#define SM_SE    98304       // 1024 f32
#define SM_SXP   102400      // 256 f32
#define SM_RED   103424      // 128 x 4 x 3 f32
#define SM_TOTAL 109568

// ---------------- prep: fp16 of (-2E), ||e||^2 ------------------------------
__global__ void prep_kernel(const float* __restrict__ emb) {
    int k = blockIdx.x, d = threadIdx.x;
    g_eh[k * D_ + d] = __float2half(-2.0f * emb[k * D_ + d]);
    if (d == 0) {
        const float* r = emb + (size_t)k * D_;
        float s = 0.f;
        for (int i = 0; i < D_; ++i) { float v = r[i]; s = fmaf(v, v, s); }
        g_enorm[k] = s;
        if (k == 0) g_fixn = 0;
    }
}

// ---------------- HMMA argmin (single fp16 product) -------------------------
__global__ __launch_bounds__(256, 2)
void argmin_kernel(const float* __restrict__ x) {
    extern __shared__ char smem[];
    const uint32_t sb = smem_u32(smem);
    float* sSe  = (float*)(smem + SM_SE);
    float* sSxp = (float*)(smem + SM_SXP);
    float* red  = (float*)(smem + SM_RED);

    const int tid  = threadIdx.x;
    const int lane = tid & 31;
    const int w    = tid >> 5;
    const int wm   = w & 1;        // pixel half (rows 0-63 / 64-127)
    const int wn   = w >> 1;       // code group (4 x 32 within a pass)
    const int b    = blockIdx.x >> 5;
    const int c0   = (blockIdx.x & 31) * 128;

    for (int i = tid; i < K_; i += 256) sSe[i] = g_enorm[i];

    // prefetch E (pass0, chunk0) into buffer 0
    {
        #pragma unroll
        for (int i = 0; i < 4; ++i) {
            int idx = tid + i * 256;
            int r = idx >> 3, s = idx & 7;
            uint32_t dst = (uint32_t)((r >> 3) * 1024 + (r & 7) * 128 +
                                      ((s * 16) ^ ((r & 7) << 4)));
            cp16(sb + SM_E + dst, g_eh + (size_t)r * D_ + s * 8);
        }
        CP_COMMIT();
    }

    // stage X tile [128 x 256] fp16, SW128 K-major
    {
        const int p = tid & 127, half = tid >> 7;
        const float* xb = x + (size_t)b * (D_ * HW_) + c0 + p;
        const uint32_t rowbase = (uint32_t)((p >> 3) * 1024 + (p & 7) * 128);
        const uint32_t rx = (uint32_t)((p & 7) << 4);
        float Sx = 0.f;
        for (int d0 = half * 128; d0 < half * 128 + 128; d0 += 8) {
            float v[8];
            #pragma unroll
            for (int i = 0; i < 8; ++i) v[i] = xb[(size_t)(d0 + i) * HW_];
            #pragma unroll
            for (int i = 0; i < 8; ++i) Sx = fmaf(v[i], v[i], Sx);
            uint32_t hp[4];
            #pragma unroll
            for (int i = 0; i < 4; ++i) {
                __half h0 = __float2half(v[2*i]);
                __half h1 = __float2half(v[2*i+1]);
                hp[i] = (uint32_t)__half_as_ushort(h0) |
                        ((uint32_t)__half_as_ushort(h1) << 16);
            }
            uint32_t off = (uint32_t)(d0 >> 6) * 16384u + rowbase +
                           (((uint32_t)(d0 & 63) * 2u) ^ rx);
            *(uint4*)(smem + SM_XHI + off) = make_uint4(hp[0], hp[1], hp[2], hp[3]);
        }
        sSxp[half * 128 + p] = Sx;
    }
    __syncthreads();

    float sx[8];
    #pragma unroll
    for (int s = 0; s < 8; ++s) {
        int pix = wm * 64 + (s >> 1) * 16 + (lane >> 2) + (s & 1) * 8;
        sx[s] = sSxp[pix] + sSxp[128 + pix];
    }

    uint32_t aOff[4], aXor[4], bOff[4], bXor[4];
    #pragma unroll
    for (int mt = 0; mt < 4; ++mt) {
        int r = wm * 64 + mt * 16 + (lane & 7) + ((lane >> 3) & 1) * 8;
        aOff[mt] = (uint32_t)((r >> 3) * 1024 + (r & 7) * 128);
        aXor[mt] = (uint32_t)((r & 7) << 4);
    }
    #pragma unroll
    for (int nt = 0; nt < 4; ++nt) {
        int n = wn * 32 + nt * 8 + (lane & 7);
        bOff[nt] = (uint32_t)((n >> 3) * 1024 + (n & 7) * 128);
        bXor[nt] = (uint32_t)((n & 7) << 4);
    }
    const uint32_t adB = (lane >> 4) ? 16u : 0u;
    const uint32_t bdB = ((lane >> 3) & 1) ? 16u : 0u;

    float m1r[8], m2r[8]; int i1r[8];
    #pragma unroll
    for (int s = 0; s < 8; ++s) { m1r[s] = 3.4e38f; m2r[s] = 3.4e38f; i1r[s] = 0; }

    float acc[4][4][4];

    for (int seg = 0; seg < 32; ++seg) {         // seg = pass*4 + chunk
        const int ch = seg & 3;
        if (seg < 31) {
            const int np = (seg + 1) >> 2, nc = (seg + 1) & 3;
            const __half* Eh = g_eh + (size_t)np * 128 * D_ + nc * 64;
            uint32_t ebase = sb + SM_E + (uint32_t)((seg + 1) & 1) * 16384u;
            #pragma unroll
            for (int i = 0; i < 4; ++i) {
                int idx = tid + i * 256;
                int r = idx >> 3, s = idx & 7;
                uint32_t dst = (uint32_t)((r >> 3) * 1024 + (r & 7) * 128 +
                                          ((s * 16) ^ ((r & 7) << 4)));
                cp16(ebase + dst, Eh + (size_t)r * D_ + s * 8);
            }
            CP_COMMIT();
            CP_WAIT1();
        } else {
            CP_WAIT0();
        }
        __syncthreads();

        if (ch == 0) {
            #pragma unroll
            for (int mt = 0; mt < 4; ++mt)
                #pragma unroll
                for (int nt = 0; nt < 4; ++nt)
                    #pragma unroll
                    for (int q = 0; q < 4; ++q) acc[mt][nt][q] = 0.f;
        }

        const uint32_t eh  = sb + SM_E + (uint32_t)(seg & 1) * 16384u;
        const uint32_t xco = (uint32_t)ch * 16384u;

        #pragma unroll
        for (int ks = 0; ks < 4; ++ks) {
            const uint32_t dA = (uint32_t)(ks * 32) + adB;
            const uint32_t dB = (uint32_t)(ks * 32) + bdB;
            uint32_t bh[4][2], ah[4][4];
            #pragma unroll
            for (int nt = 0; nt < 4; ++nt)
                ldsm2(bh[nt], eh + bOff[nt] + (dB ^ bXor[nt]));
            #pragma unroll
            for (int mt = 0; mt < 4; ++mt)
                ldsm4(ah[mt], sb + SM_XHI + xco + aOff[mt] + (dA ^ aXor[mt]));
            #pragma unroll
            for (int mt = 0; mt < 4; ++mt)
                #pragma unroll
                for (int nt = 0; nt < 4; ++nt)
                    mma16816(acc[mt][nt], ah[mt], bh[nt]);
        }

        if (ch == 3) {
            const int pass = seg >> 2;
            const int cbase = pass * 128 + wn * 32 + 2 * (lane & 3);
            #pragma unroll
            for (int nt = 0; nt < 4; ++nt) {
                const int code0 = cbase + nt * 8;
                const float se0 = sSe[code0], se1 = sSe[code0 + 1];
                #pragma unroll
                for (int mt = 0; mt < 4; ++mt) {
                    const int s0 = mt * 2, s1 = mt * 2 + 1;
                    float v;
                    v = sx[s0] + se0 + acc[mt][nt][0];
                    if (v < m1r[s0]) { m2r[s0] = m1r[s0]; m1r[s0] = v; i1r[s0] = code0; }
                    else if (v < m2r[s0]) m2r[s0] = v;
                    v = sx[s0] + se1 + acc[mt][nt][1];
                    if (v < m1r[s0]) { m2r[s0] = m1r[s0]; m1r[s0] = v; i1r[s0] = code0 + 1; }
                    else if (v < m2r[s0]) m2r[s0] = v;
                    v = sx[s1] + se0 + acc[mt][nt][2];
                    if (v < m1r[s1]) { m2r[s1] = m1r[s1]; m1r[s1] = v; i1r[s1] = code0; }
                    else if (v < m2r[s1]) m2r[s1] = v;
                    v = sx[s1] + se1 + acc[mt][nt][3];
                    if (v < m1r[s1]) { m2r[s1] = m1r[s1]; m1r[s1] = v; i1r[s1] = code0 + 1; }
                    else if (v < m2r[s1]) m2r[s1] = v;
                }
            }
        }
        __syncthreads();
    }

    #pragma unroll
    for (int s = 0; s < 8; ++s) {
        float a1 = m1r[s], a2 = m2r[s]; int ai = i1r[s];
        #pragma unroll
        for (int ofs = 1; ofs <= 2; ofs <<= 1) {
            float v1 = __shfl_xor_sync(0xffffffffu, a1, ofs);
            float v2 = __shfl_xor_sync(0xffffffffu, a2, ofs);
            int   vi = __shfl_xor_sync(0xffffffffu, ai, ofs);
            if (v1 < a1 || (v1 == a1 && vi < ai)) { a2 = fminf(a1, v2); a1 = v1; ai = vi; }
            else                                  { a2 = fminf(a2, v1); }
        }
        if ((lane & 3) == 0) {
            int pix = wm * 64 + (s >> 1) * 16 + (lane >> 2) + (s & 1) * 8;
            red[(pix * 4 + wn) * 3 + 0] = a1;
            red[(pix * 4 + wn) * 3 + 1] = a2;
            red[(pix * 4 + wn) * 3 + 2] = __int_as_float(ai);
        }
    }
    __syncthreads();

    if (tid < 128) {
        float a1 = red[(tid * 4) * 3], a2 = red[(tid * 4) * 3 + 1];
        int   ai = __float_as_int(red[(tid * 4) * 3 + 2]);
        #pragma unroll
        for (int q = 1; q < 4; ++q) {
            float v1 = red[(tid * 4 + q) * 3], v2 = red[(tid * 4 + q) * 3 + 1];
            int   vi = __float_as_int(red[(tid * 4 + q) * 3 + 2]);
            if (v1 < a1 || (v1 == a1 && vi < ai)) { a2 = fminf(a1, v2); a1 = v1; ai = vi; }
            else                                  { a2 = fminf(a2, v1); }
        }
        const int row = b * HW_ + c0 + tid;
        g_idx[row] = ai;
        if (a2 - a1 < THRESH) {
            int pos = atomicAdd(&g_fixn, 1);
            g_fixlist[pos] = row;
        }
    }
}

// ---------------- exact-fp32 fixup of near-tie rows -------------------------
#define FX_SX   0
#define FX_ED   16448
#define FX_SSX  (FX_ED + 69632)
#define FX_ROWS (FX_SSX + 64)
#define FX_TOTAL (FX_ROWS + 64)

__global__ __launch_bounds__(256)
void fixup_kernel(const float* __restrict__ x, const float* __restrict__ emb) {
    extern __shared__ char fsm[];
    float* sx  = (float*)(fsm + FX_SX);    // [16][257]
    float* ed  = (float*)(fsm + FX_ED);    // [256][68]
    float* sSx = (float*)(fsm + FX_SSX);
    int*   rws = (int*)(fsm + FX_ROWS);

    const int n = g_fixn;
    const int tid = threadIdx.x;
    const int r  = tid >> 4;
    const int tc = tid & 15;

    for (int base = blockIdx.x * 16; base < n; base += gridDim.x * 16) {
        if (tid < 16) rws[tid] = (base + tid < n) ? g_fixlist[base + tid] : -1;
        __syncthreads();
        for (int i = tid; i < 16 * D_; i += 256) {
            int rr = i >> 8, d = i & 255;
            int row = rws[rr];
            int row_c = (row < 0) ? 0 : row;
            int bb = row_c >> 12, pix = row_c & 4095;
            sx[rr * 257 + d] = x[(size_t)bb * (D_ * HW_) + (size_t)d * HW_ + pix];
        }
        __syncthreads();
        if (tc == 0) {
            float s = 0.f;
            for (int d = 0; d < D_; ++d) { float v = sx[r * 257 + d]; s = fmaf(v, v, s); }
            sSx[r] = s;
        }
        float m = 3.4e38f; int bi = 0;
        for (int cb = 0; cb < 16; ++cb) {
            __syncthreads();
            {
                int cc = tid >> 2, dseg = (tid & 3) * 64;
                const float* er = emb + (size_t)(cb * 64 + cc) * D_ + dseg;
                for (int i = 0; i < 64; i += 4) {
                    float4 v = *(const float4*)(er + i);
                    ed[(dseg + i)     * 68 + cc] = v.x;
                    ed[(dseg + i + 1) * 68 + cc] = v.y;
                    ed[(dseg + i + 2) * 68 + cc] = v.z;
                    ed[(dseg + i + 3) * 68 + cc] = v.w;
                }
            }
            __syncthreads();
            float a0 = 0.f, a1 = 0.f, a2 = 0.f, a3 = 0.f;
            const float* xr = sx + r * 257;
            for (int d = 0; d < D_; ++d) {
                float xv = xr[d];
                float4 ev = *(const float4*)(ed + d * 68 + tc * 4);
                a0 = fmaf(ev.x, xv, a0);
                a1 = fmaf(ev.y, xv, a1);
                a2 = fmaf(ev.z, xv, a2);
                a3 = fmaf(ev.w, xv, a3);
            }
            float accv[4] = {a0, a1, a2, a3};
            float Sxr = sSx[r];
            #pragma unroll
            for (int j = 0; j < 4; ++j) {
                int code = cb * 64 + tc * 4 + j;
                float s = fmaf(-2.f, accv[j], Sxr + g_enorm[code]);
                if (s < m) { m = s; bi = code; }
            }
        }
        #pragma unroll
        for (int off = 8; off; off >>= 1) {
            float ov = __shfl_down_sync(0xffffffffu, m, off, 16);
            int   oi = __shfl_down_sync(0xffffffffu, bi, off, 16);
            if (ov < m || (ov == m && oi < bi)) { m = ov; bi = oi; }
        }
        if (tc == 0 && rws[r] >= 0) g_idx[rws[r]] = bi;
        __syncthreads();
    }
}

// ---------------- gather: smem-staged E rows + STE output + loss ------------
__global__ __launch_bounds__(256)
void gather_kernel(const float* __restrict__ x, const float* __restrict__ emb,
                   float* __restrict__ outT) {
    __shared__ int   sidx[128];
    __shared__ float ech[128 * 65];
    __shared__ float ws[8];
    const int tid = threadIdx.x;
    const int b   = blockIdx.y;
    const int c0  = blockIdx.x * 128;
    if (tid < 128) sidx[tid] = g_idx[b * HW_ + c0 + tid];
    __syncthreads();

    const int c  = tid & 127;
    const int dh = tid >> 7;
    size_t base = (size_t)b * (D_ * HW_) + c0 + c;

    float lsum = 0.f;
    for (int d0 = 0; d0 < D_; d0 += 64) {
        // stage E[sidx[r]][d0..d0+64) coalesced into ech[r][dd] (stride 65)
        #pragma unroll 8
        for (int i = 0; i < 32; ++i) {
            int idx = tid + i * 256;
            int rr = idx >> 6, dd = idx & 63;
            ech[rr * 65 + dd] = emb[(size_t)sidx[rr] * D_ + d0 + dd];
        }
        __syncthreads();
        #pragma unroll 8
        for (int d = dh; d < 64; d += 2) {
            float q  = ech[c * 65 + d];
            size_t off = base + (size_t)(d0 + d) * HW_;
            float xv = x[off];
            float df = q - xv;
            lsum = fmaf(df, df, lsum);
            outT[off] = xv + df;          // STE: fl(x + fl(q - x))
        }
        __syncthreads();
    }
    #pragma unroll
    for (int o = 16; o; o >>= 1) lsum += __shfl_down_sync(0xffffffffu, lsum, o);
    if ((tid & 31) == 0) ws[tid >> 5] = lsum;
    __syncthreads();
    if (tid == 0) {
        float s = 0.f;
        #pragma unroll
        for (int i = 0; i < 8; ++i) s += ws[i];
        g_bsum[blockIdx.y * 32 + blockIdx.x] = s;
    }
}

// ---------------- loss finalize --------------------------------------------
__global__ void finalize_kernel(const float* beta, float* out) {
    __shared__ float sh[256];
    int tid = threadIdx.x;
    float s = 0.f;
    for (int i = tid; i < 1024; i += 256) s += g_bsum[i];
    sh[tid] = s; __syncthreads();
    for (int o = 128; o; o >>= 1) {
        if (tid < o) sh[tid] += sh[tid + o];
        __syncthreads();
    }
    if (tid == 0) {
        float bv = 0.25f;
        if (beta) {
            float f = *beta;
            if (f > 0.0f && f < 100.0f) bv = f;
            else {
                double dv = *(const double*)beta;
                if (dv > 0.0 && dv < 100.0) bv = (float)dv;
            }
        }
        out[0] = (1.0f + bv) * (sh[0] / 33554432.0f);
    }
}

// ---------------------------------------------------------------------------
extern "C" void kernel_launch(void* const* d_in, const int* in_sizes, int n_in,
                              void* d_out, int out_size) {
    (void)in_sizes;
    const float* x    = (const float*)d_in[0];
    const float* emb  = (const float*)d_in[1];
    const float* beta = (n_in > 2) ? (const float*)d_in[2] : nullptr;
    float* out = (float*)d_out;

    int off = out_size - TENSOR_ELEMS;
    if (off < 0) off = 0;

    cudaFuncSetAttribute(argmin_kernel,
                         cudaFuncAttributeMaxDynamicSharedMemorySize, SM_TOTAL);
    cudaFuncSetAttribute(fixup_kernel,
                         cudaFuncAttributeMaxDynamicSharedMemorySize, FX_TOTAL);

    prep_kernel<<<K_, 256>>>(emb);
    argmin_kernel<<<1024, 256, SM_TOTAL>>>(x);
    fixup_kernel<<<256, 256, FX_TOTAL>>>(x, emb);
    gather_kernel<<<dim3(32, 32), 256>>>(x, emb, out + off);
    if (off >= 1) finalize_kernel<<<1, 256>>>(beta, out);
}

// round 9
// speedup vs baseline: 2.4364x; 1.0773x over previous
#include <cuda_runtime.h>
#include <cuda_fp16.h>
#include <cstdint>

#define B_    32
#define D_    256
#define HW_   4096
#define K_    1024
#define NROWS (B_ * HW_)
#define TENSOR_ELEMS (B_ * D_ * HW_)
#define THRESH 1.2e-4f

__device__ __half g_eh[K_ * D_];     // fp16 of (-2*E), k-major rows
__device__ float g_enorm[K_];
__device__ int   g_idx[NROWS];
__device__ float g_bsum[1024];
__device__ int   g_fixn;
__device__ int   g_fixlist[NROWS];

// ---------------- PTX helpers (plain sm_80-level, no 'a' features) ----------
__device__ __forceinline__ uint32_t smem_u32(const void* p) {
    uint32_t a;
    asm("{ .reg .u64 t; cvta.to.shared.u64 t, %1; cvt.u32.u64 %0, t; }" : "=r"(a) : "l"(p));
    return a;
}
__device__ __forceinline__ void cp16(uint32_t dst, const void* src) {
    asm volatile("cp.async.cg.shared.global [%0], [%1], 16;" :: "r"(dst), "l"(src) : "memory");
}
#define CP_COMMIT() asm volatile("cp.async.commit_group;" ::: "memory")
#define CP_WAIT0()  asm volatile("cp.async.wait_group 0;" ::: "memory")
#define CP_WAIT1()  asm volatile("cp.async.wait_group 1;" ::: "memory")

__device__ __forceinline__ void ldsm4(uint32_t* r, uint32_t addr) {
    asm volatile("ldmatrix.sync.aligned.m8n8.x4.shared.b16 {%0,%1,%2,%3}, [%4];"
                 : "=r"(r[0]), "=r"(r[1]), "=r"(r[2]), "=r"(r[3]) : "r"(addr));
}
__device__ __forceinline__ void mma16816(float* c, const uint32_t* a, const uint32_t* b) {
    asm volatile("mma.sync.aligned.m16n8k16.row.col.f32.f16.f16.f32 "
                 "{%0,%1,%2,%3}, {%4,%5,%6,%7}, {%8,%9}, {%0,%1,%2,%3};"
                 : "+f"(c[0]), "+f"(c[1]), "+f"(c[2]), "+f"(c[3])
                 : "r"(a[0]), "r"(a[1]), "r"(a[2]), "r"(a[3]), "r"(b[0]), "r"(b[1]));
}

// smem layout (bytes): X 64K | B 2x32K | Se 4K | Sxp 1K | red 6K
#define SM_XHI   0
#define SM_E     65536
#define SM_SE    131072
#define SM_SXP   135168
#define SM_RED   136192
#define SM_TOTAL 142336

// ---------------- prep: fp16 of (-2E), ||e||^2 ------------------------------
__global__ void prep_kernel(const float* __restrict__ emb) {
    int k = blockIdx.x, d = threadIdx.x;
    g_eh[k * D_ + d] = __float2half(-2.0f * emb[k * D_ + d]);
    if (d == 0) {
        const float* r = emb + (size_t)k * D_;
        float s = 0.f;
        for (int i = 0; i < D_; ++i) { float v = r[i]; s = fmaf(v, v, s); }
        g_enorm[k] = s;
        if (k == 0) g_fixn = 0;
    }
}

// stage one 128-code x 128-d fp16 tile into a 32KB buffer (8 cp16/thread)
__device__ __forceinline__ void stage_B(uint32_t ebase, const __half* Eptr, int tid) {
    #pragma unroll
    for (int i = 0; i < 8; ++i) {
        int idx = tid + i * 256;
        int r = idx >> 4, s = idx & 15;            // r: code row, s: 8-half col (d = s*8)
        uint32_t dst = (uint32_t)((s & 8) << 11) +                 // 64-d sub-chunk
                       (uint32_t)((r >> 3) * 1024 + (r & 7) * 128 +
                                  (((s & 7) * 16) ^ ((r & 7) << 4)));
        cp16(ebase + dst, Eptr + (size_t)r * D_ + s * 8);
    }
    CP_COMMIT();
}

// ---------------- HMMA argmin (single fp16 product) -------------------------
__global__ __launch_bounds__(256)
void argmin_kernel(const float* __restrict__ x) {
    extern __shared__ char smem[];
    const uint32_t sb = smem_u32(smem);
    float* sSe  = (float*)(smem + SM_SE);
    float* sSxp = (float*)(smem + SM_SXP);
    float* red  = (float*)(smem + SM_RED);

    const int tid  = threadIdx.x;
    const int lane = tid & 31;
    const int w    = tid >> 5;
    const int wm   = w & 1;        // pixel half (rows 0-63 / 64-127)
    const int wn   = w >> 1;       // code group (4 x 32 within a pass)
    const int b    = blockIdx.x >> 5;
    const int c0   = (blockIdx.x & 31) * 128;

    for (int i = tid; i < K_; i += 256) sSe[i] = g_enorm[i];

    // prefetch seg0 (pass0, dchunk0) into buffer 0
    stage_B(sb + SM_E, g_eh, tid);

    // stage X tile [128 x 256] fp16, SW128 K-major (4 x 16KB d-chunks)
    {
        const int p = tid & 127, half = tid >> 7;
        const float* xb = x + (size_t)b * (D_ * HW_) + c0 + p;
        const uint32_t rowbase = (uint32_t)((p >> 3) * 1024 + (p & 7) * 128);
        const uint32_t rx = (uint32_t)((p & 7) << 4);
        float Sx = 0.f;
        for (int d0 = half * 128; d0 < half * 128 + 128; d0 += 8) {
            float v[8];
            #pragma unroll
            for (int i = 0; i < 8; ++i) v[i] = xb[(size_t)(d0 + i) * HW_];
            #pragma unroll
            for (int i = 0; i < 8; ++i) Sx = fmaf(v[i], v[i], Sx);
            uint32_t hp[4];
            #pragma unroll
            for (int i = 0; i < 4; ++i) {
                __half h0 = __float2half(v[2*i]);
                __half h1 = __float2half(v[2*i+1]);
                hp[i] = (uint32_t)__half_as_ushort(h0) |
                        ((uint32_t)__half_as_ushort(h1) << 16);
            }
            uint32_t off = (uint32_t)(d0 >> 6) * 16384u + rowbase +
                           (((uint32_t)(d0 & 63) * 2u) ^ rx);
            *(uint4*)(smem + SM_XHI + off) = make_uint4(hp[0], hp[1], hp[2], hp[3]);
        }
        sSxp[half * 128 + p] = Sx;
    }
    __syncthreads();

    float sx[8];
    #pragma unroll
    for (int s = 0; s < 8; ++s) {
        int pix = wm * 64 + (s >> 1) * 16 + (lane >> 2) + (s & 1) * 8;
        sx[s] = sSxp[pix] + sSxp[128 + pix];
    }

    // A-side ldmatrix constants (16x16 tiles over 64 pixel rows)
    uint32_t aOff[4], aXor[4];
    #pragma unroll
    for (int mt = 0; mt < 4; ++mt) {
        int r = wm * 64 + mt * 16 + (lane & 7) + ((lane >> 3) & 1) * 8;
        aOff[mt] = (uint32_t)((r >> 3) * 1024 + (r & 7) * 128);
        aXor[mt] = (uint32_t)((r & 7) << 4);
    }
    const uint32_t adB = (lane >> 4) ? 16u : 0u;
    // B-side: pair two 8-col tiles per ldmatrix.x4
    uint32_t bpOff[2], bpXor[2];
    #pragma unroll
    for (int p = 0; p < 2; ++p) {
        int n = wn * 32 + p * 16 + ((lane >> 4) << 3) + (lane & 7);
        bpOff[p] = (uint32_t)((n >> 3) * 1024 + (n & 7) * 128);
        bpXor[p] = (uint32_t)((n & 7) << 4);
    }
    const uint32_t kB = (uint32_t)(((lane >> 3) & 1) << 4);

    float m1r[8], m2r[8]; int i1r[8];
    #pragma unroll
    for (int s = 0; s < 8; ++s) { m1r[s] = 3.4e38f; m2r[s] = 3.4e38f; i1r[s] = 0; }

    float acc[4][4][4];

    for (int seg = 0; seg < 16; ++seg) {        // seg = pass*2 + dchunk
        const int ch = seg & 1;
        if (seg < 15) {
            const int np = (seg + 1) >> 1, nc = (seg + 1) & 1;
            stage_B(sb + SM_E + (uint32_t)((seg + 1) & 1) * 32768u,
                    g_eh + (size_t)np * 128 * D_ + nc * 128, tid);
            CP_WAIT1();
        } else {
            CP_WAIT0();
        }
        __syncthreads();

        if (ch == 0) {
            #pragma unroll
            for (int mt = 0; mt < 4; ++mt)
                #pragma unroll
                for (int nt = 0; nt < 4; ++nt)
                    #pragma unroll
                    for (int q = 0; q < 4; ++q) acc[mt][nt][q] = 0.f;
        }

        const uint32_t eh = sb + SM_E + (uint32_t)(seg & 1) * 32768u;

        #pragma unroll
        for (int ks = 0; ks < 8; ++ks) {
            const uint32_t sub  = (uint32_t)(ks >> 2) * 16384u;
            const uint32_t ksl  = (uint32_t)(ks & 3) * 32u;
            const uint32_t xco  = (uint32_t)(ch * 2 + (ks >> 2)) * 16384u;
            const uint32_t dA   = ksl + adB;
            uint32_t bh[4][2], ah[4][4];
            #pragma unroll
            for (int p = 0; p < 2; ++p) {
                uint32_t r4[4];
                ldsm4(r4, eh + sub + bpOff[p] + ((ksl + kB) ^ bpXor[p]));
                bh[2*p][0] = r4[0]; bh[2*p][1] = r4[1];
                bh[2*p+1][0] = r4[2]; bh[2*p+1][1] = r4[3];
            }
            #pragma unroll
            for (int mt = 0; mt < 4; ++mt)
                ldsm4(ah[mt], sb + SM_XHI + xco + aOff[mt] + (dA ^ aXor[mt]));
            #pragma unroll
            for (int mt = 0; mt < 4; ++mt)
                #pragma unroll
                for (int nt = 0; nt < 4; ++nt)
                    mma16816(acc[mt][nt], ah[mt], bh[nt]);
        }

        if (ch == 1) {
            const int pass = seg >> 1;
            const int cbase = pass * 128 + wn * 32 + 2 * (lane & 3);
            #pragma unroll
            for (int nt = 0; nt < 4; ++nt) {
                const int code0 = cbase + nt * 8;
                const float se0 = sSe[code0], se1 = sSe[code0 + 1];
                #pragma unroll
                for (int mt = 0; mt < 4; ++mt) {
                    const int s0 = mt * 2, s1 = mt * 2 + 1;
                    float v;
                    v = sx[s0] + se0 + acc[mt][nt][0];
                    if (v < m1r[s0]) { m2r[s0] = m1r[s0]; m1r[s0] = v; i1r[s0] = code0; }
                    else if (v < m2r[s0]) m2r[s0] = v;
                    v = sx[s0] + se1 + acc[mt][nt][1];
                    if (v < m1r[s0]) { m2r[s0] = m1r[s0]; m1r[s0] = v; i1r[s0] = code0 + 1; }
                    else if (v < m2r[s0]) m2r[s0] = v;
                    v = sx[s1] + se0 + acc[mt][nt][2];
                    if (v < m1r[s1]) { m2r[s1] = m1r[s1]; m1r[s1] = v; i1r[s1] = code0; }
                    else if (v < m2r[s1]) m2r[s1] = v;
                    v = sx[s1] + se1 + acc[mt][nt][3];
                    if (v < m1r[s1]) { m2r[s1] = m1r[s1]; m1r[s1] = v; i1r[s1] = code0 + 1; }
                    else if (v < m2r[s1]) m2r[s1] = v;
                }
            }
        }
        __syncthreads();
    }

    #pragma unroll
    for (int s = 0; s < 8; ++s) {
        float a1 = m1r[s], a2 = m2r[s]; int ai = i1r[s];
        #pragma unroll
        for (int ofs = 1; ofs <= 2; ofs <<= 1) {
            float v1 = __shfl_xor_sync(0xffffffffu, a1, ofs);
            float v2 = __shfl_xor_sync(0xffffffffu, a2, ofs);
            int   vi = __shfl_xor_sync(0xffffffffu, ai, ofs);
            if (v1 < a1 || (v1 == a1 && vi < ai)) { a2 = fminf(a1, v2); a1 = v1; ai = vi; }
            else                                  { a2 = fminf(a2, v1); }
        }
        if ((lane & 3) == 0) {
            int pix = wm * 64 + (s >> 1) * 16 + (lane >> 2) + (s & 1) * 8;
            red[(pix * 4 + wn) * 3 + 0] = a1;
            red[(pix * 4 + wn) * 3 + 1] = a2;
            red[(pix * 4 + wn) * 3 + 2] = __int_as_float(ai);
        }
    }
    __syncthreads();

    if (tid < 128) {
        float a1 = red[(tid * 4) * 3], a2 = red[(tid * 4) * 3 + 1];
        int   ai = __float_as_int(red[(tid * 4) * 3 + 2]);
        #pragma unroll
        for (int q = 1; q < 4; ++q) {
            float v1 = red[(tid * 4 + q) * 3], v2 = red[(tid * 4 + q) * 3 + 1];
            int   vi = __float_as_int(red[(tid * 4 + q) * 3 + 2]);
            if (v1 < a1 || (v1 == a1 && vi < ai)) { a2 = fminf(a1, v2); a1 = v1; ai = vi; }
            else                                  { a2 = fminf(a2, v1); }
        }
        const int row = b * HW_ + c0 + tid;
        g_idx[row] = ai;
        if (a2 - a1 < THRESH) {
            int pos = atomicAdd(&g_fixn, 1);
            g_fixlist[pos] = row;
        }
    }
}

// ---------------- exact-fp32 fixup of near-tie rows -------------------------
#define FX_SX   0
#define FX_ED   16448
#define FX_SSX  (FX_ED + 69632)
#define FX_ROWS (FX_SSX + 64)
#define FX_TOTAL (FX_ROWS + 64)

__global__ __launch_bounds__(256)
void fixup_kernel(const float* __restrict__ x, const float* __restrict__ emb) {
    extern __shared__ char fsm[];
    float* sx  = (float*)(fsm + FX_SX);    // [16][257]
    float* ed  = (float*)(fsm + FX_ED);    // [256][68]
    float* sSx = (float*)(fsm + FX_SSX);
    int*   rws = (int*)(fsm + FX_ROWS);

    const int n = g_fixn;
    const int tid = threadIdx.x;
    const int r  = tid >> 4;
    const int tc = tid & 15;

    for (int base = blockIdx.x * 16; base < n; base += gridDim.x * 16) {
        if (tid < 16) rws[tid] = (base + tid < n) ? g_fixlist[base + tid] : -1;
        __syncthreads();
        for (int i = tid; i < 16 * D_; i += 256) {
            int rr = i >> 8, d = i & 255;
            int row = rws[rr];
            int row_c = (row < 0) ? 0 : row;
            int bb = row_c >> 12, pix = row_c & 4095;
            sx[rr * 257 + d] = x[(size_t)bb * (D_ * HW_) + (size_t)d * HW_ + pix];
        }
        __syncthreads();
        if (tc == 0) {
            float s = 0.f;
            for (int d = 0; d < D_; ++d) { float v = sx[r * 257 + d]; s = fmaf(v, v, s); }
            sSx[r] = s;
        }
        float m = 3.4e38f; int bi = 0;
        for (int cb = 0; cb < 16; ++cb) {
            __syncthreads();
            {
                int cc = tid >> 2, dseg = (tid & 3) * 64;
                const float* er = emb + (size_t)(cb * 64 + cc) * D_ + dseg;
                for (int i = 0; i < 64; i += 4) {
                    float4 v = *(const float4*)(er + i);
                    ed[(dseg + i)     * 68 + cc] = v.x;
                    ed[(dseg + i + 1) * 68 + cc] = v.y;
                    ed[(dseg + i + 2) * 68 + cc] = v.z;
                    ed[(dseg + i + 3) * 68 + cc] = v.w;
                }
            }
            __syncthreads();
            float a0 = 0.f, a1 = 0.f, a2 = 0.f, a3 = 0.f;
            const float* xr = sx + r * 257;
            for (int d = 0; d < D_; ++d) {
                float xv = xr[d];
                float4 ev = *(const float4*)(ed + d * 68 + tc * 4);
                a0 = fmaf(ev.x, xv, a0);
                a1 = fmaf(ev.y, xv, a1);
                a2 = fmaf(ev.z, xv, a2);
                a3 = fmaf(ev.w, xv, a3);
            }
            float accv[4] = {a0, a1, a2, a3};
            float Sxr = sSx[r];
            #pragma unroll
            for (int j = 0; j < 4; ++j) {
                int code = cb * 64 + tc * 4 + j;
                float s = fmaf(-2.f, accv[j], Sxr + g_enorm[code]);
                if (s < m) { m = s; bi = code; }
            }
        }
        #pragma unroll
        for (int off = 8; off; off >>= 1) {
            float ov = __shfl_down_sync(0xffffffffu, m, off, 16);
            int   oi = __shfl_down_sync(0xffffffffu, bi, off, 16);
            if (ov < m || (ov == m && oi < bi)) { m = ov; bi = oi; }
        }
        if (tc == 0 && rws[r] >= 0) g_idx[rws[r]] = bi;
        __syncthreads();
    }
}

// ---------------- gather: transposed smem, float4 loads, scalar stores ------
#define G_SIDX  0
#define G_WS    512
#define G_ET    1024                       // et[d][pixel], row stride 132 floats
#define G_TOTAL (G_ET + 128 * 132 * 4)

__global__ __launch_bounds__(256)
void gather_kernel(const float* __restrict__ x, const float* __restrict__ emb,
                   float* __restrict__ outT) {
    extern __shared__ char gsm[];
    int*   sidx = (int*)(gsm + G_SIDX);
    float* ws   = (float*)(gsm + G_WS);
    float* et   = (float*)(gsm + G_ET);

    const int tid = threadIdx.x;
    const int b   = blockIdx.y;
    const int c0  = blockIdx.x * 128;
    if (tid < 128) sidx[tid] = g_idx[b * HW_ + c0 + tid];
    __syncthreads();

    const int pg = (tid & 31) * 4;     // 4-pixel group within warp
    const int dg = tid >> 5;           // warp -> 16 d rows per chunk
    float lsum = 0.f;

    for (int d0 = 0; d0 < D_; d0 += 128) {
        if (d0) __syncthreads();
        // stage emb rows transposed: et[d][p]  (pixel-fast -> STS conflict-free)
        #pragma unroll 4
        for (int i = 0; i < 16; ++i) {
            int idx = tid + i * 256;
            int p = idx & 127, f4 = idx >> 7;
            float4 v = *(const float4*)(emb + (size_t)sidx[p] * D_ + d0 + f4 * 4);
            et[(f4 * 4 + 0) * 132 + p] = v.x;
            et[(f4 * 4 + 1) * 132 + p] = v.y;
            et[(f4 * 4 + 2) * 132 + p] = v.z;
            et[(f4 * 4 + 3) * 132 + p] = v.w;
        }
        __syncthreads();
        #pragma unroll 4
        for (int j = 0; j < 16; ++j) {
            int d = dg * 16 + j;
            size_t off = (size_t)b * (D_ * HW_) + (size_t)(d0 + d) * HW_ + c0 + pg;
            float4 xv = *(const float4*)(x + off);         // x is 16B-aligned
            float4 q  = *(const float4*)(et + d * 132 + pg);
            float dx0 = q.x - xv.x, dx1 = q.y - xv.y;
            float dx2 = q.z - xv.z, dx3 = q.w - xv.w;
            lsum = fmaf(dx0, dx0, lsum); lsum = fmaf(dx1, dx1, lsum);
            lsum = fmaf(dx2, dx2, lsum); lsum = fmaf(dx3, dx3, lsum);
            // outT may be out+1 (loss first) -> only 4B-aligned: scalar stores
            float* op = outT + off;
            op[0] = xv.x + dx0;           // STE: fl(x + fl(q - x))
            op[1] = xv.y + dx1;
            op[2] = xv.z + dx2;
            op[3] = xv.w + dx3;
        }
    }
    #pragma unroll
    for (int o = 16; o; o >>= 1) lsum += __shfl_down_sync(0xffffffffu, lsum, o);
    if ((tid & 31) == 0) ws[tid >> 5] = lsum;
    __syncthreads();
    if (tid == 0) {
        float s = 0.f;
        #pragma unroll
        for (int i = 0; i < 8; ++i) s += ws[i];
        g_bsum[blockIdx.y * 32 + blockIdx.x] = s;
    }
}

// ---------------- loss finalize --------------------------------------------
__global__ void finalize_kernel(const float* beta, float* out) {
    __shared__ float sh[256];
    int tid = threadIdx.x;
    float s = 0.f;
    for (int i = tid; i < 1024; i += 256) s += g_bsum[i];
    sh[tid] = s; __syncthreads();
    for (int o = 128; o; o >>= 1) {
        if (tid < o) sh[tid] += sh[tid + o];
        __syncthreads();
    }
    if (tid == 0) {
        float bv = 0.25f;
        if (beta) {
            float f = *beta;
            if (f > 0.0f && f < 100.0f) bv = f;
            else {
                double dv = *(const double*)beta;
                if (dv > 0.0 && dv < 100.0) bv = (float)dv;
            }
        }
        out[0] = (1.0f + bv) * (sh[0] / 33554432.0f);
    }
}

// ---------------------------------------------------------------------------
extern "C" void kernel_launch(void* const* d_in, const int* in_sizes, int n_in,
                              void* d_out, int out_size) {
    (void)in_sizes;
    const float* x    = (const float*)d_in[0];
    const float* emb  = (const float*)d_in[1];
    const float* beta = (n_in > 2) ? (const float*)d_in[2] : nullptr;
    float* out = (float*)d_out;

    int off = out_size - TENSOR_ELEMS;
    if (off < 0) off = 0;

    cudaFuncSetAttribute(argmin_kernel,
                         cudaFuncAttributeMaxDynamicSharedMemorySize, SM_TOTAL);
    cudaFuncSetAttribute(fixup_kernel,
                         cudaFuncAttributeMaxDynamicSharedMemorySize, FX_TOTAL);
    cudaFuncSetAttribute(gather_kernel,
                         cudaFuncAttributeMaxDynamicSharedMemorySize, G_TOTAL);

    prep_kernel<<<K_, 256>>>(emb);
    argmin_kernel<<<1024, 256, SM_TOTAL>>>(x);
    fixup_kernel<<<256, 256, FX_TOTAL>>>(x, emb);
    gather_kernel<<<dim3(32, 32), 256, G_TOTAL>>>(x, emb, out + off);
    if (off >= 1) finalize_kernel<<<1, 256>>>(beta, out);
}

// round 10
// speedup vs baseline: 2.4775x; 1.0169x over previous
#include <cuda_runtime.h>
#include <cuda_fp16.h>
#include <cstdint>

#define B_    32
#define D_    256
#define HW_   4096
#define K_    1024
#define NROWS (B_ * HW_)
#define TENSOR_ELEMS (B_ * D_ * HW_)
#define THRESH 1.5e-4f

__device__ __half g_eh[K_ * D_];     // fp16 of (-2*E), k-major rows
__device__ float g_enorm[K_];
__device__ int   g_idx[NROWS];
__device__ float g_bsum[1024];
__device__ int   g_fixn;
__device__ int   g_fixlist[NROWS];

// ---------------- PTX helpers (plain sm_80-level, no 'a' features) ----------
__device__ __forceinline__ uint32_t smem_u32(const void* p) {
    uint32_t a;
    asm("{ .reg .u64 t; cvta.to.shared.u64 t, %1; cvt.u32.u64 %0, t; }" : "=r"(a) : "l"(p));
    return a;
}
__device__ __forceinline__ void cp16(uint32_t dst, const void* src) {
    asm volatile("cp.async.cg.shared.global [%0], [%1], 16;" :: "r"(dst), "l"(src) : "memory");
}
#define CP_COMMIT() asm volatile("cp.async.commit_group;" ::: "memory")
#define CP_WAIT0()  asm volatile("cp.async.wait_group 0;" ::: "memory")
#define CP_WAIT1()  asm volatile("cp.async.wait_group 1;" ::: "memory")
#define CP_WAIT2()  asm volatile("cp.async.wait_group 2;" ::: "memory")

__device__ __forceinline__ void ldsm4(uint32_t* r, uint32_t addr) {
    asm volatile("ldmatrix.sync.aligned.m8n8.x4.shared.b16 {%0,%1,%2,%3}, [%4];"
                 : "=r"(r[0]), "=r"(r[1]), "=r"(r[2]), "=r"(r[3]) : "r"(addr));
}
__device__ __forceinline__ void mma16816(float* c, const uint32_t* a, const uint32_t* b) {
    asm volatile("mma.sync.aligned.m16n8k16.row.col.f32.f16.f16.f32 "
                 "{%0,%1,%2,%3}, {%4,%5,%6,%7}, {%8,%9}, {%0,%1,%2,%3};"
                 : "+f"(c[0]), "+f"(c[1]), "+f"(c[2]), "+f"(c[3])
                 : "r"(a[0]), "r"(a[1]), "r"(a[2]), "r"(a[3]), "r"(b[0]), "r"(b[1]));
}

// smem layout (bytes): X 64K | B 4x32K | Se 4K | red 6K
#define SM_XHI   0
#define SM_E     65536
#define SM_SE    196608
#define SM_RED   200704
#define SM_TOTAL 206848

// ---------------- prep: fp16 of (-2E), ||e||^2 ------------------------------
__global__ void prep_kernel(const float* __restrict__ emb) {
    int k = blockIdx.x, d = threadIdx.x;
    g_eh[k * D_ + d] = __float2half(-2.0f * emb[k * D_ + d]);
    if (d == 0) {
        const float* r = emb + (size_t)k * D_;
        float s = 0.f;
        for (int i = 0; i < D_; ++i) { float v = r[i]; s = fmaf(v, v, s); }
        g_enorm[k] = s;
        if (k == 0) g_fixn = 0;
    }
}

// stage one 128-code x 128-d fp16 tile into a 32KB buffer (8 cp16/thread)
__device__ __forceinline__ void stage_B(uint32_t ebase, const __half* Eptr, int tid) {
    #pragma unroll
    for (int i = 0; i < 8; ++i) {
        int idx = tid + i * 256;
        int r = idx >> 4, s = idx & 15;            // r: code row, s: 8-half col (d = s*8)
        uint32_t dst = (uint32_t)((s & 8) << 11) +                 // 64-d sub-chunk
                       (uint32_t)((r >> 3) * 1024 + (r & 7) * 128 +
                                  (((s & 7) * 16) ^ ((r & 7) << 4)));
        cp16(ebase + dst, Eptr + (size_t)r * D_ + s * 8);
    }
    CP_COMMIT();
}

// ---------------- HMMA argmin (single fp16 product) -------------------------
__global__ __launch_bounds__(256)
void argmin_kernel(const float* __restrict__ x) {
    extern __shared__ char smem[];
    const uint32_t sb = smem_u32(smem);
    float* sSe  = (float*)(smem + SM_SE);
    float* red  = (float*)(smem + SM_RED);

    const int tid  = threadIdx.x;
    const int lane = tid & 31;
    const int w    = tid >> 5;
    const int wm   = w & 1;        // pixel half (rows 0-63 / 64-127)
    const int wn   = w >> 1;       // code group (4 x 32 within a pass)
    const int b    = blockIdx.x >> 5;
    const int c0   = (blockIdx.x & 31) * 128;

    for (int i = tid; i < K_; i += 256) sSe[i] = g_enorm[i];

    // prefetch seg0, seg1 (pass0 chunks 0,1) into buffers 0,1
    stage_B(sb + SM_E,          g_eh,       tid);
    stage_B(sb + SM_E + 32768u, g_eh + 128, tid);

    // stage X tile [128 x 256] fp16, SW128 K-major (4 x 16KB d-chunks)
    {
        const int p = tid & 127, half = tid >> 7;
        const float* xb = x + (size_t)b * (D_ * HW_) + c0 + p;
        const uint32_t rowbase = (uint32_t)((p >> 3) * 1024 + (p & 7) * 128);
        const uint32_t rx = (uint32_t)((p & 7) << 4);
        for (int d0 = half * 128; d0 < half * 128 + 128; d0 += 8) {
            float v[8];
            #pragma unroll
            for (int i = 0; i < 8; ++i) v[i] = xb[(size_t)(d0 + i) * HW_];
            uint32_t hp[4];
            #pragma unroll
            for (int i = 0; i < 4; ++i) {
                __half h0 = __float2half(v[2*i]);
                __half h1 = __float2half(v[2*i+1]);
                hp[i] = (uint32_t)__half_as_ushort(h0) |
                        ((uint32_t)__half_as_ushort(h1) << 16);
            }
            uint32_t off = (uint32_t)(d0 >> 6) * 16384u + rowbase +
                           (((uint32_t)(d0 & 63) * 2u) ^ rx);
            *(uint4*)(smem + SM_XHI + off) = make_uint4(hp[0], hp[1], hp[2], hp[3]);
        }
    }

    // A-side ldmatrix constants (16x16 tiles over 64 pixel rows)
    uint32_t aOff[4], aXor[4];
    #pragma unroll
    for (int mt = 0; mt < 4; ++mt) {
        int r = wm * 64 + mt * 16 + (lane & 7) + ((lane >> 3) & 1) * 8;
        aOff[mt] = (uint32_t)((r >> 3) * 1024 + (r & 7) * 128);
        aXor[mt] = (uint32_t)((r & 7) << 4);
    }
    const uint32_t adB = (lane >> 4) ? 16u : 0u;
    // B-side: pair two 8-col tiles per ldmatrix.x4
    uint32_t bpOff[2], bpXor[2];
    #pragma unroll
    for (int p = 0; p < 2; ++p) {
        int n = wn * 32 + p * 16 + ((lane >> 4) << 3) + (lane & 7);
        bpOff[p] = (uint32_t)((n >> 3) * 1024 + (n & 7) * 128);
        bpXor[p] = (uint32_t)((n & 7) << 4);
    }
    const uint32_t kB = (uint32_t)(((lane >> 3) & 1) << 4);

    float m1r[8], m2r[8]; int i1r[8];
    #pragma unroll
    for (int s = 0; s < 8; ++s) { m1r[s] = 3.4e38f; m2r[s] = 3.4e38f; i1r[s] = 0; }

    float acc[4][4][4];

    for (int seg = 0; seg < 16; ++seg) {        // seg = pass*2 + dchunk
        const int ch = seg & 1;
        // distance-2 prefetch into buffer (seg+2)%4; single barrier per seg
        if (seg < 14) {
            const int ns = seg + 2;
            stage_B(sb + SM_E + (uint32_t)(ns & 3) * 32768u,
                    g_eh + (size_t)(ns >> 1) * 128 * D_ + (ns & 1) * 128, tid);
            CP_WAIT2();
        } else if (seg == 14) {
            CP_WAIT1();
        } else {
            CP_WAIT0();
        }
        __syncthreads();

        if (ch == 0) {
            #pragma unroll
            for (int mt = 0; mt < 4; ++mt)
                #pragma unroll
                for (int nt = 0; nt < 4; ++nt)
                    #pragma unroll
                    for (int q = 0; q < 4; ++q) acc[mt][nt][q] = 0.f;
        }

        const uint32_t eh = sb + SM_E + (uint32_t)(seg & 3) * 32768u;

        #pragma unroll
        for (int ks = 0; ks < 8; ++ks) {
            const uint32_t sub  = (uint32_t)(ks >> 2) * 16384u;
            const uint32_t ksl  = (uint32_t)(ks & 3) * 32u;
            const uint32_t xco  = (uint32_t)(ch * 2 + (ks >> 2)) * 16384u;
            const uint32_t dA   = ksl + adB;
            uint32_t bh[4][2], ah[4][4];
            #pragma unroll
            for (int p = 0; p < 2; ++p) {
                uint32_t r4[4];
                ldsm4(r4, eh + sub + bpOff[p] + ((ksl + kB) ^ bpXor[p]));
                bh[2*p][0] = r4[0]; bh[2*p][1] = r4[1];
                bh[2*p+1][0] = r4[2]; bh[2*p+1][1] = r4[3];
            }
            #pragma unroll
            for (int mt = 0; mt < 4; ++mt)
                ldsm4(ah[mt], sb + SM_XHI + xco + aOff[mt] + (dA ^ aXor[mt]));
            #pragma unroll
            for (int mt = 0; mt < 4; ++mt)
                #pragma unroll
                for (int nt = 0; nt < 4; ++nt)
                    mma16816(acc[mt][nt], ah[mt], bh[nt]);
        }

        if (ch == 1) {
            // fold scores: s = Se + dot (Sx dropped: rank-invariant; fixup
            // recomputes the exact reference formula for near-ties)
            const int pass = seg >> 1;
            const int cbase = pass * 128 + wn * 32 + 2 * (lane & 3);
            #pragma unroll
            for (int nt = 0; nt < 4; ++nt) {
                const int code0 = cbase + nt * 8;
                const float se0 = sSe[code0], se1 = sSe[code0 + 1];
                #pragma unroll
                for (int mt = 0; mt < 4; ++mt) {
                    const int s0 = mt * 2, s1 = mt * 2 + 1;
                    float v;
                    v = se0 + acc[mt][nt][0];
                    if (v < m1r[s0]) { m2r[s0] = m1r[s0]; m1r[s0] = v; i1r[s0] = code0; }
                    else if (v < m2r[s0]) m2r[s0] = v;
                    v = se1 + acc[mt][nt][1];
                    if (v < m1r[s0]) { m2r[s0] = m1r[s0]; m1r[s0] = v; i1r[s0] = code0 + 1; }
                    else if (v < m2r[s0]) m2r[s0] = v;
                    v = se0 + acc[mt][nt][2];
                    if (v < m1r[s1]) { m2r[s1] = m1r[s1]; m1r[s1] = v; i1r[s1] = code0; }
                    else if (v < m2r[s1]) m2r[s1] = v;
                    v = se1 + acc[mt][nt][3];
                    if (v < m1r[s1]) { m2r[s1] = m1r[s1]; m1r[s1] = v; i1r[s1] = code0 + 1; }
                    else if (v < m2r[s1]) m2r[s1] = v;
                }
            }
        }
    }

    __syncthreads();
    #pragma unroll
    for (int s = 0; s < 8; ++s) {
        float a1 = m1r[s], a2 = m2r[s]; int ai = i1r[s];
        #pragma unroll
        for (int ofs = 1; ofs <= 2; ofs <<= 1) {
            float v1 = __shfl_xor_sync(0xffffffffu, a1, ofs);
            float v2 = __shfl_xor_sync(0xffffffffu, a2, ofs);
            int   vi = __shfl_xor_sync(0xffffffffu, ai, ofs);
            if (v1 < a1 || (v1 == a1 && vi < ai)) { a2 = fminf(a1, v2); a1 = v1; ai = vi; }
            else                                  { a2 = fminf(a2, v1); }
        }
        if ((lane & 3) == 0) {
            int pix = wm * 64 + (s >> 1) * 16 + (lane >> 2) + (s & 1) * 8;
            red[(pix * 4 + wn) * 3 + 0] = a1;
            red[(pix * 4 + wn) * 3 + 1] = a2;
            red[(pix * 4 + wn) * 3 + 2] = __int_as_float(ai);
        }
    }
    __syncthreads();

    if (tid < 128) {
        float a1 = red[(tid * 4) * 3], a2 = red[(tid * 4) * 3 + 1];
        int   ai = __float_as_int(red[(tid * 4) * 3 + 2]);
        #pragma unroll
        for (int q = 1; q < 4; ++q) {
            float v1 = red[(tid * 4 + q) * 3], v2 = red[(tid * 4 + q) * 3 + 1];
            int   vi = __float_as_int(red[(tid * 4 + q) * 3 + 2]);
            if (v1 < a1 || (v1 == a1 && vi < ai)) { a2 = fminf(a1, v2); a1 = v1; ai = vi; }
            else                                  { a2 = fminf(a2, v1); }
        }
        const int row = b * HW_ + c0 + tid;
        g_idx[row] = ai;
        if (a2 - a1 < THRESH) {
            int pos = atomicAdd(&g_fixn, 1);
            g_fixlist[pos] = row;
        }
    }
}

// ---------------- exact-fp32 fixup of near-tie rows -------------------------
#define FX_SX   0
#define FX_ED   16448
#define FX_SSX  (FX_ED + 69632)
#define FX_ROWS (FX_SSX + 64)
#define FX_TOTAL (FX_ROWS + 64)

__global__ __launch_bounds__(256)
void fixup_kernel(const float* __restrict__ x, const float* __restrict__ emb) {
    extern __shared__ char fsm[];
    float* sx  = (float*)(fsm + FX_SX);    // [16][257]
    float* ed  = (float*)(fsm + FX_ED);    // [256][68]
    float* sSx = (float*)(fsm + FX_SSX);
    int*   rws = (int*)(fsm + FX_ROWS);

    const int n = g_fixn;
    const int tid = threadIdx.x;
    const int r  = tid >> 4;
    const int tc = tid & 15;

    for (int base = blockIdx.x * 16; base < n; base += gridDim.x * 16) {
        if (tid < 16) rws[tid] = (base + tid < n) ? g_fixlist[base + tid] : -1;
        __syncthreads();
        for (int i = tid; i < 16 * D_; i += 256) {
            int rr = i >> 8, d = i & 255;
            int row = rws[rr];
            int row_c = (row < 0) ? 0 : row;
            int bb = row_c >> 12, pix = row_c & 4095;
            sx[rr * 257 + d] = x[(size_t)bb * (D_ * HW_) + (size_t)d * HW_ + pix];
        }
        __syncthreads();
        if (tc == 0) {
            float s = 0.f;
            for (int d = 0; d < D_; ++d) { float v = sx[r * 257 + d]; s = fmaf(v, v, s); }
            sSx[r] = s;
        }
        float m = 3.4e38f; int bi = 0;
        for (int cb = 0; cb < 16; ++cb) {
            __syncthreads();
            {
                int cc = tid >> 2, dseg = (tid & 3) * 64;
                const float* er = emb + (size_t)(cb * 64 + cc) * D_ + dseg;
                for (int i = 0; i < 64; i += 4) {
                    float4 v = *(const float4*)(er + i);
                    ed[(dseg + i)     * 68 + cc] = v.x;
                    ed[(dseg + i + 1) * 68 + cc] = v.y;
                    ed[(dseg + i + 2) * 68 + cc] = v.z;
                    ed[(dseg + i + 3) * 68 + cc] = v.w;
                }
            }
            __syncthreads();
            float a0 = 0.f, a1 = 0.f, a2 = 0.f, a3 = 0.f;
            const float* xr = sx + r * 257;
            for (int d = 0; d < D_; ++d) {
                float xv = xr[d];
                float4 ev = *(const float4*)(ed + d * 68 + tc * 4);
                a0 = fmaf(ev.x, xv, a0);
                a1 = fmaf(ev.y, xv, a1);
                a2 = fmaf(ev.z, xv, a2);
                a3 = fmaf(ev.w, xv, a3);
            }
            float accv[4] = {a0, a1, a2, a3};
            float Sxr = sSx[r];
            #pragma unroll
            for (int j = 0; j < 4; ++j) {
                int code = cb * 64 + tc * 4 + j;
                float s = fmaf(-2.f, accv[j], Sxr + g_enorm[code]);
                if (s < m) { m = s; bi = code; }
            }
        }
        #pragma unroll
        for (int off = 8; off; off >>= 1) {
            float ov = __shfl_down_sync(0xffffffffu, m, off, 16);
            int   oi = __shfl_down_sync(0xffffffffu, bi, off, 16);
            if (ov < m || (ov == m && oi < bi)) { m = ov; bi = oi; }
        }
        if (tc == 0 && rws[r] >= 0) g_idx[rws[r]] = bi;
        __syncthreads();
    }
}

// ---------------- gather: 64-d chunks, batched loads (MLP up), scalar stores -
#define G_SIDX  0
#define G_WS    512
#define G_ET    1024                       // et[d][pixel], 64 x 132 floats
#define G_TOTAL (G_ET + 64 * 132 * 4)

__global__ __launch_bounds__(256)
void gather_kernel(const float* __restrict__ x, const float* __restrict__ emb,
                   float* __restrict__ outT) {
    extern __shared__ char gsm[];
    int*   sidx = (int*)(gsm + G_SIDX);
    float* ws   = (float*)(gsm + G_WS);
    float* et   = (float*)(gsm + G_ET);

    const int tid = threadIdx.x;
    const int b   = blockIdx.y;
    const int c0  = blockIdx.x * 128;
    if (tid < 128) sidx[tid] = g_idx[b * HW_ + c0 + tid];
    __syncthreads();

    const int pg = (tid & 31) * 4;     // 4-pixel group within warp
    const int dg = tid >> 5;           // warp -> 8 d rows per 64-d chunk
    float lsum = 0.f;

    for (int d0 = 0; d0 < D_; d0 += 64) {
        if (d0) __syncthreads();
        // stage emb rows transposed: et[d][p] (pixel-fast -> STS conflict-free)
        #pragma unroll
        for (int i = 0; i < 8; ++i) {
            int idx = tid + i * 256;
            int p = idx & 127, f4 = idx >> 7;
            float4 v = *(const float4*)(emb + (size_t)sidx[p] * D_ + d0 + f4 * 4);
            et[(f4 * 4 + 0) * 132 + p] = v.x;
            et[(f4 * 4 + 1) * 132 + p] = v.y;
            et[(f4 * 4 + 2) * 132 + p] = v.z;
            et[(f4 * 4 + 3) * 132 + p] = v.w;
        }
        __syncthreads();
        // two batches of 4 d-rows; loads batched first for MLP
        #pragma unroll
        for (int h = 0; h < 2; ++h) {
            float4 xv[4], q[4];
            size_t offs[4];
            #pragma unroll
            for (int j = 0; j < 4; ++j) {
                int d = dg * 8 + h * 4 + j;
                offs[j] = (size_t)b * (D_ * HW_) + (size_t)(d0 + d) * HW_ + c0 + pg;
                xv[j] = *(const float4*)(x + offs[j]);
            }
            #pragma unroll
            for (int j = 0; j < 4; ++j)
                q[j] = *(const float4*)(et + (dg * 8 + h * 4 + j) * 132 + pg);
            #pragma unroll
            for (int j = 0; j < 4; ++j) {
                float dx0 = q[j].x - xv[j].x, dx1 = q[j].y - xv[j].y;
                float dx2 = q[j].z - xv[j].z, dx3 = q[j].w - xv[j].w;
                lsum = fmaf(dx0, dx0, lsum); lsum = fmaf(dx1, dx1, lsum);
                lsum = fmaf(dx2, dx2, lsum); lsum = fmaf(dx3, dx3, lsum);
                float* op = outT + offs[j];        // 4B-aligned only: scalar STG
                op[0] = xv[j].x + dx0;             // STE: fl(x + fl(q - x))
                op[1] = xv[j].y + dx1;
                op[2] = xv[j].z + dx2;
                op[3] = xv[j].w + dx3;
            }
        }
    }
    #pragma unroll
    for (int o = 16; o; o >>= 1) lsum += __shfl_down_sync(0xffffffffu, lsum, o);
    if ((tid & 31) == 0) ws[tid >> 5] = lsum;
    __syncthreads();
    if (tid == 0) {
        float s = 0.f;
        #pragma unroll
        for (int i = 0; i < 8; ++i) s += ws[i];
        g_bsum[blockIdx.y * 32 + blockIdx.x] = s;
    }
}

// ---------------- loss finalize --------------------------------------------
__global__ void finalize_kernel(const float* beta, float* out) {
    __shared__ float sh[256];
    int tid = threadIdx.x;
    float s = 0.f;
    for (int i = tid; i < 1024; i += 256) s += g_bsum[i];
    sh[tid] = s; __syncthreads();
    for (int o = 128; o; o >>= 1) {
        if (tid < o) sh[tid] += sh[tid + o];
        __syncthreads();
    }
    if (tid == 0) {
        float bv = 0.25f;
        if (beta) {
            float f = *beta;
            if (f > 0.0f && f < 100.0f) bv = f;
            else {
                double dv = *(const double*)beta;
                if (dv > 0.0 && dv < 100.0) bv = (float)dv;
            }
        }
        out[0] = (1.0f + bv) * (sh[0] / 33554432.0f);
    }
}

// ---------------------------------------------------------------------------
extern "C" void kernel_launch(void* const* d_in, const int* in_sizes, int n_in,
                              void* d_out, int out_size) {
    (void)in_sizes;
    const float* x    = (const float*)d_in[0];
    const float* emb  = (const float*)d_in[1];
    const float* beta = (n_in > 2) ? (const float*)d_in[2] : nullptr;
    float* out = (float*)d_out;

    int off = out_size - TENSOR_ELEMS;
    if (off < 0) off = 0;

    cudaFuncSetAttribute(argmin_kernel,
                         cudaFuncAttributeMaxDynamicSharedMemorySize, SM_TOTAL);
    cudaFuncSetAttribute(fixup_kernel,
                         cudaFuncAttributeMaxDynamicSharedMemorySize, FX_TOTAL);
    cudaFuncSetAttribute(gather_kernel,
                         cudaFuncAttributeMaxDynamicSharedMemorySize, G_TOTAL);

    prep_kernel<<<K_, 256>>>(emb);
    argmin_kernel<<<1024, 256, SM_TOTAL>>>(x);
    fixup_kernel<<<256, 256, FX_TOTAL>>>(x, emb);
    gather_kernel<<<dim3(32, 32), 256, G_TOTAL>>>(x, emb, out + off);
    if (off >= 1) finalize_kernel<<<1, 256>>>(beta, out);
}

// round 12
// speedup vs baseline: 2.8728x; 1.1595x over previous
#include <cuda_runtime.h>
#include <cuda_fp16.h>
#include <cstdint>

#define B_    32
#define D_    256
#define HW_   4096
#define K_    1024
#define NROWS (B_ * HW_)
#define TENSOR_ELEMS (B_ * D_ * HW_)
#define THRESH 1.5e-4f

__device__ __half g_eh[K_ * D_];     // fp16 of (-2*E), k-major rows
__device__ float g_enorm[K_];
__device__ int   g_idx[NROWS];
__device__ float g_bsum[1024];
__device__ int   g_fixn;
__device__ int   g_fixlist[NROWS];

// ---------------- PTX helpers (plain sm_80-level, no 'a' features) ----------
__device__ __forceinline__ uint32_t smem_u32(const void* p) {
    uint32_t a;
    asm("{ .reg .u64 t; cvta.to.shared.u64 t, %1; cvt.u32.u64 %0, t; }" : "=r"(a) : "l"(p));
    return a;
}
__device__ __forceinline__ void cp16(uint32_t dst, const void* src) {
    asm volatile("cp.async.cg.shared.global [%0], [%1], 16;" :: "r"(dst), "l"(src) : "memory");
}
#define CP_COMMIT() asm volatile("cp.async.commit_group;" ::: "memory")
#define CP_WAIT0()  asm volatile("cp.async.wait_group 0;" ::: "memory")

__device__ __forceinline__ void ldsm4(uint32_t* r, uint32_t addr) {
    asm volatile("ldmatrix.sync.aligned.m8n8.x4.shared.b16 {%0,%1,%2,%3}, [%4];"
                 : "=r"(r[0]), "=r"(r[1]), "=r"(r[2]), "=r"(r[3]) : "r"(addr));
}
__device__ __forceinline__ void mma16816(float* c, const uint32_t* a, const uint32_t* b) {
    asm volatile("mma.sync.aligned.m16n8k16.row.col.f32.f16.f16.f32 "
                 "{%0,%1,%2,%3}, {%4,%5,%6,%7}, {%8,%9}, {%0,%1,%2,%3};"
                 : "+f"(c[0]), "+f"(c[1]), "+f"(c[2]), "+f"(c[3])
                 : "r"(a[0]), "r"(a[1]), "r"(a[2]), "r"(a[3]), "r"(b[0]), "r"(b[1]));
}

// smem layout (bytes): X 32K | B 2x32K | Se 4K | red 3K  -> 103 KB, occ 2
#define SM_XHI   0
#define SM_E     32768
#define SM_SE    98304
#define SM_RED   102400
#define SM_TOTAL 105472

// ---------------- prep: fp16 of (-2E), ||e||^2 ------------------------------
__global__ void prep_kernel(const float* __restrict__ emb) {
    int k = blockIdx.x, d = threadIdx.x;
    g_eh[k * D_ + d] = __float2half(-2.0f * emb[k * D_ + d]);
    if (d == 0) {
        const float* r = emb + (size_t)k * D_;
        float s = 0.f;
        for (int i = 0; i < D_; ++i) { float v = r[i]; s = fmaf(v, v, s); }
        g_enorm[k] = s;
        if (k == 0) g_fixn = 0;
    }
}

// stage one 128-code x 128-d fp16 tile into a 32KB buffer (8 cp16/thread)
__device__ __forceinline__ void stage_B(uint32_t ebase, const __half* Eptr, int tid) {
    #pragma unroll
    for (int i = 0; i < 8; ++i) {
        int idx = tid + i * 256;
        int r = idx >> 4, s = idx & 15;            // r: code row, s: 8-half col (d = s*8)
        uint32_t dst = (uint32_t)((s & 8) << 11) +                 // 64-d sub-chunk
                       (uint32_t)((r >> 3) * 1024 + (r & 7) * 128 +
                                  (((s & 7) * 16) ^ ((r & 7) << 4)));
        cp16(ebase + dst, Eptr + (size_t)r * D_ + s * 8);
    }
    CP_COMMIT();
}

// ---------------- HMMA argmin: 64 pixels/CTA, occupancy 2 -------------------
__global__ __launch_bounds__(256, 2)
void argmin_kernel(const float* __restrict__ x) {
    extern __shared__ char smem[];
    const uint32_t sb = smem_u32(smem);
    float* sSe  = (float*)(smem + SM_SE);
    float* red  = (float*)(smem + SM_RED);

    const int tid  = threadIdx.x;
    const int lane = tid & 31;
    const int w    = tid >> 5;
    const int wm   = w & 1;        // pixel half (rows 0-31 / 32-63)
    const int wn   = w >> 1;       // code group (4 x 32 within a 128-code pass)
    const int b    = blockIdx.x >> 6;
    const int c0   = (blockIdx.x & 63) * 64;

    for (int i = tid; i < K_; i += 256) sSe[i] = g_enorm[i];

    // prefetch seg0 (pass0, chunk0) into buffer 0
    stage_B(sb + SM_E, g_eh, tid);

    // stage X tile [64 pixels x 256 d] fp16, SW128 K-major (4 x 8KB d-chunks)
    {
        const int p = tid & 63, half = tid >> 6;   // half in 0..3: 64 d each
        const float* xb = x + (size_t)b * (D_ * HW_) + c0 + p;
        const uint32_t rowbase = (uint32_t)((p >> 3) * 1024 + (p & 7) * 128);
        const uint32_t rx = (uint32_t)((p & 7) << 4);
        for (int d0 = half * 64; d0 < half * 64 + 64; d0 += 8) {
            float v[8];
            #pragma unroll
            for (int i = 0; i < 8; ++i) v[i] = xb[(size_t)(d0 + i) * HW_];
            uint32_t hp[4];
            #pragma unroll
            for (int i = 0; i < 4; ++i) {
                __half h0 = __float2half(v[2*i]);
                __half h1 = __float2half(v[2*i+1]);
                hp[i] = (uint32_t)__half_as_ushort(h0) |
                        ((uint32_t)__half_as_ushort(h1) << 16);
            }
            uint32_t off = (uint32_t)(d0 >> 6) * 8192u + rowbase +
                           (((uint32_t)(d0 & 63) * 2u) ^ rx);
            *(uint4*)(smem + SM_XHI + off) = make_uint4(hp[0], hp[1], hp[2], hp[3]);
        }
    }

    // A-side ldmatrix constants (2 x 16x16 tiles over this warp's 32 rows)
    uint32_t aOff[2], aXor[2];
    #pragma unroll
    for (int mt = 0; mt < 2; ++mt) {
        int r = wm * 32 + mt * 16 + (lane & 7) + ((lane >> 3) & 1) * 8;
        aOff[mt] = (uint32_t)((r >> 3) * 1024 + (r & 7) * 128);
        aXor[mt] = (uint32_t)((r & 7) << 4);
    }
    const uint32_t adB = (lane >> 4) ? 16u : 0u;
    // B-side: pair two 8-col tiles per ldmatrix.x4
    uint32_t bpOff[2], bpXor[2];
    #pragma unroll
    for (int p = 0; p < 2; ++p) {
        int n = wn * 32 + p * 16 + ((lane >> 4) << 3) + (lane & 7);
        bpOff[p] = (uint32_t)((n >> 3) * 1024 + (n & 7) * 128);
        bpXor[p] = (uint32_t)((n & 7) << 4);
    }
    const uint32_t kB = (uint32_t)(((lane >> 3) & 1) << 4);

    float m1r[4], m2r[4]; int i1r[4];
    #pragma unroll
    for (int s = 0; s < 4; ++s) { m1r[s] = 3.4e38f; m2r[s] = 3.4e38f; i1r[s] = 0; }

    float acc[2][4][4];

    for (int seg = 0; seg < 16; ++seg) {        // seg = pass*2 + dchunk
        const int ch = seg & 1;
        // Hazard-safe single barrier: WAIT0 completes the group staged last
        // seg; the barrier (a) makes it visible to all warps and (b) orders
        // all of last seg's reads BEFORE this seg's cp.async overwrites.
        CP_WAIT0();
        __syncthreads();
        if (seg < 15) {
            const int ns = seg + 1;
            stage_B(sb + SM_E + (uint32_t)(ns & 1) * 32768u,
                    g_eh + (size_t)(ns >> 1) * 128 * D_ + (ns & 1) * 128, tid);
        }

        if (ch == 0) {
            #pragma unroll
            for (int mt = 0; mt < 2; ++mt)
                #pragma unroll
                for (int nt = 0; nt < 4; ++nt)
                    #pragma unroll
                    for (int q = 0; q < 4; ++q) acc[mt][nt][q] = 0.f;
        }

        const uint32_t eh = sb + SM_E + (uint32_t)(seg & 1) * 32768u;

        #pragma unroll
        for (int ks = 0; ks < 8; ++ks) {
            const uint32_t sub  = (uint32_t)(ks >> 2) * 16384u;
            const uint32_t ksl  = (uint32_t)(ks & 3) * 32u;
            const uint32_t xco  = (uint32_t)(ch * 2 + (ks >> 2)) * 8192u;
            const uint32_t dA   = ksl + adB;
            uint32_t bh[4][2], ah[2][4];
            #pragma unroll
            for (int p = 0; p < 2; ++p) {
                uint32_t r4[4];
                ldsm4(r4, eh + sub + bpOff[p] + ((ksl + kB) ^ bpXor[p]));
                bh[2*p][0] = r4[0]; bh[2*p][1] = r4[1];
                bh[2*p+1][0] = r4[2]; bh[2*p+1][1] = r4[3];
            }
            #pragma unroll
            for (int mt = 0; mt < 2; ++mt)
                ldsm4(ah[mt], sb + SM_XHI + xco + aOff[mt] + (dA ^ aXor[mt]));
            #pragma unroll
            for (int mt = 0; mt < 2; ++mt)
                #pragma unroll
                for (int nt = 0; nt < 4; ++nt)
                    mma16816(acc[mt][nt], ah[mt], bh[nt]);
        }

        if (ch == 1) {
            // fold scores: s = Se + dot (Sx dropped: rank-invariant; fixup
            // recomputes the exact reference formula for near-ties)
            const int pass = seg >> 1;
            const int cbase = pass * 128 + wn * 32 + 2 * (lane & 3);
            #pragma unroll
            for (int nt = 0; nt < 4; ++nt) {
                const int code0 = cbase + nt * 8;
                const float se0 = sSe[code0], se1 = sSe[code0 + 1];
                #pragma unroll
                for (int mt = 0; mt < 2; ++mt) {
                    const int s0 = mt * 2, s1 = mt * 2 + 1;
                    float v;
                    v = se0 + acc[mt][nt][0];
                    if (v < m1r[s0]) { m2r[s0] = m1r[s0]; m1r[s0] = v; i1r[s0] = code0; }
                    else if (v < m2r[s0]) m2r[s0] = v;
                    v = se1 + acc[mt][nt][1];
                    if (v < m1r[s0]) { m2r[s0] = m1r[s0]; m1r[s0] = v; i1r[s0] = code0 + 1; }
                    else if (v < m2r[s0]) m2r[s0] = v;
                    v = se0 + acc[mt][nt][2];
                    if (v < m1r[s1]) { m2r[s1] = m1r[s1]; m1r[s1] = v; i1r[s1] = code0; }
                    else if (v < m2r[s1]) m2r[s1] = v;
                    v = se1 + acc[mt][nt][3];
                    if (v < m1r[s1]) { m2r[s1] = m1r[s1]; m1r[s1] = v; i1r[s1] = code0 + 1; }
                    else if (v < m2r[s1]) m2r[s1] = v;
                }
            }
        }
    }

    __syncthreads();
    #pragma unroll
    for (int s = 0; s < 4; ++s) {
        float a1 = m1r[s], a2 = m2r[s]; int ai = i1r[s];
        #pragma unroll
        for (int ofs = 1; ofs <= 2; ofs <<= 1) {
            float v1 = __shfl_xor_sync(0xffffffffu, a1, ofs);
            float v2 = __shfl_xor_sync(0xffffffffu, a2, ofs);
            int   vi = __shfl_xor_sync(0xffffffffu, ai, ofs);
            if (v1 < a1 || (v1 == a1 && vi < ai)) { a2 = fminf(a1, v2); a1 = v1; ai = vi; }
            else                                  { a2 = fminf(a2, v1); }
        }
        if ((lane & 3) == 0) {
            int pix = wm * 32 + (s >> 1) * 16 + (lane >> 2) + (s & 1) * 8;
            red[(pix * 4 + wn) * 3 + 0] = a1;
            red[(pix * 4 + wn) * 3 + 1] = a2;
            red[(pix * 4 + wn) * 3 + 2] = __int_as_float(ai);
        }
    }
    __syncthreads();

    if (tid < 64) {
        float a1 = red[(tid * 4) * 3], a2 = red[(tid * 4) * 3 + 1];
        int   ai = __float_as_int(red[(tid * 4) * 3 + 2]);
        #pragma unroll
        for (int q = 1; q < 4; ++q) {
            float v1 = red[(tid * 4 + q) * 3], v2 = red[(tid * 4 + q) * 3 + 1];
            int   vi = __float_as_int(red[(tid * 4 + q) * 3 + 2]);
            if (v1 < a1 || (v1 == a1 && vi < ai)) { a2 = fminf(a1, v2); a1 = v1; ai = vi; }
            else                                  { a2 = fminf(a2, v1); }
        }
        const int row = b * HW_ + c0 + tid;
        g_idx[row] = ai;
        if (a2 - a1 < THRESH) {
            int pos = atomicAdd(&g_fixn, 1);
            g_fixlist[pos] = row;
        }
    }
}

// ---------------- exact-fp32 fixup of near-tie rows -------------------------
#define FX_SX   0
#define FX_ED   16448
#define FX_SSX  (FX_ED + 69632)
#define FX_ROWS (FX_SSX + 64)
#define FX_TOTAL (FX_ROWS + 64)

__global__ __launch_bounds__(256)
void fixup_kernel(const float* __restrict__ x, const float* __restrict__ emb) {
    extern __shared__ char fsm[];
    float* sx  = (float*)(fsm + FX_SX);    // [16][257]
    float* ed  = (float*)(fsm + FX_ED);    // [256][68]
    float* sSx = (float*)(fsm + FX_SSX);
    int*   rws = (int*)(fsm + FX_ROWS);

    const int n = g_fixn;
    const int tid = threadIdx.x;
    const int r  = tid >> 4;
    const int tc = tid & 15;

    for (int base = blockIdx.x * 16; base < n; base += gridDim.x * 16) {
        if (tid < 16) rws[tid] = (base + tid < n) ? g_fixlist[base + tid] : -1;
        __syncthreads();
        for (int i = tid; i < 16 * D_; i += 256) {
            int rr = i >> 8, d = i & 255;
            int row = rws[rr];
            int row_c = (row < 0) ? 0 : row;
            int bb = row_c >> 12, pix = row_c & 4095;
            sx[rr * 257 + d] = x[(size_t)bb * (D_ * HW_) + (size_t)d * HW_ + pix];
        }
        __syncthreads();
        if (tc == 0) {
            float s = 0.f;
            for (int d = 0; d < D_; ++d) { float v = sx[r * 257 + d]; s = fmaf(v, v, s); }
            sSx[r] = s;
        }
        float m = 3.4e38f; int bi = 0;
        for (int cb = 0; cb < 16; ++cb) {
            __syncthreads();
            {
                int cc = tid >> 2, dseg = (tid & 3) * 64;
                const float* er = emb + (size_t)(cb * 64 + cc) * D_ + dseg;
                for (int i = 0; i < 64; i += 4) {
                    float4 v = *(const float4*)(er + i);
                    ed[(dseg + i)     * 68 + cc] = v.x;
                    ed[(dseg + i + 1) * 68 + cc] = v.y;
                    ed[(dseg + i + 2) * 68 + cc] = v.z;
                    ed[(dseg + i + 3) * 68 + cc] = v.w;
                }
            }
            __syncthreads();
            float a0 = 0.f, a1 = 0.f, a2 = 0.f, a3 = 0.f;
            const float* xr = sx + r * 257;
            for (int d = 0; d < D_; ++d) {
                float xv = xr[d];
                float4 ev = *(const float4*)(ed + d * 68 + tc * 4);
                a0 = fmaf(ev.x, xv, a0);
                a1 = fmaf(ev.y, xv, a1);
                a2 = fmaf(ev.z, xv, a2);
                a3 = fmaf(ev.w, xv, a3);
            }
            float accv[4] = {a0, a1, a2, a3};
            float Sxr = sSx[r];
            #pragma unroll
            for (int j = 0; j < 4; ++j) {
                int code = cb * 64 + tc * 4 + j;
                float s = fmaf(-2.f, accv[j], Sxr + g_enorm[code]);
                if (s < m) { m = s; bi = code; }
            }
        }
        #pragma unroll
        for (int off = 8; off; off >>= 1) {
            float ov = __shfl_down_sync(0xffffffffu, m, off, 16);
            int   oi = __shfl_down_sync(0xffffffffu, bi, off, 16);
            if (ov < m || (ov == m && oi < bi)) { m = ov; bi = oi; }
        }
        if (tc == 0 && rws[r] >= 0) g_idx[rws[r]] = bi;
        __syncthreads();
    }
}

// ---------------- gather: 64-d chunks, batched loads (MLP up), scalar stores -
#define G_SIDX  0
#define G_WS    512
#define G_ET    1024                       // et[d][pixel], 64 x 132 floats
#define G_TOTAL (G_ET + 64 * 132 * 4)

__global__ __launch_bounds__(256)
void gather_kernel(const float* __restrict__ x, const float* __restrict__ emb,
                   float* __restrict__ outT) {
    extern __shared__ char gsm[];
    int*   sidx = (int*)(gsm + G_SIDX);
    float* ws   = (float*)(gsm + G_WS);
    float* et   = (float*)(gsm + G_ET);

    const int tid = threadIdx.x;
    const int b   = blockIdx.y;
    const int c0  = blockIdx.x * 128;
    if (tid < 128) sidx[tid] = g_idx[b * HW_ + c0 + tid];
    __syncthreads();

    const int pg = (tid & 31) * 4;     // 4-pixel group within warp
    const int dg = tid >> 5;           // warp -> 8 d rows per 64-d chunk
    float lsum = 0.f;

    for (int d0 = 0; d0 < D_; d0 += 64) {
        if (d0) __syncthreads();
        #pragma unroll
        for (int i = 0; i < 8; ++i) {
            int idx = tid + i * 256;
            int p = idx & 127, f4 = idx >> 7;
            float4 v = *(const float4*)(emb + (size_t)sidx[p] * D_ + d0 + f4 * 4);
            et[(f4 * 4 + 0) * 132 + p] = v.x;
            et[(f4 * 4 + 1) * 132 + p] = v.y;
            et[(f4 * 4 + 2) * 132 + p] = v.z;
            et[(f4 * 4 + 3) * 132 + p] = v.w;
        }
        __syncthreads();
        #pragma unroll
        for (int h = 0; h < 2; ++h) {
            float4 xv[4], q[4];
            size_t offs[4];
            #pragma unroll
            for (int j = 0; j < 4; ++j) {
                int d = dg * 8 + h * 4 + j;
                offs[j] = (size_t)b * (D_ * HW_) + (size_t)(d0 + d) * HW_ + c0 + pg;
                xv[j] = *(const float4*)(x + offs[j]);
            }
            #pragma unroll
            for (int j = 0; j < 4; ++j)
                q[j] = *(const float4*)(et + (dg * 8 + h * 4 + j) * 132 + pg);
            #pragma unroll
            for (int j = 0; j < 4; ++j) {
                float dx0 = q[j].x - xv[j].x, dx1 = q[j].y - xv[j].y;
                float dx2 = q[j].z - xv[j].z, dx3 = q[j].w - xv[j].w;
                lsum = fmaf(dx0, dx0, lsum); lsum = fmaf(dx1, dx1, lsum);
                lsum = fmaf(dx2, dx2, lsum); lsum = fmaf(dx3, dx3, lsum);
                float* op = outT + offs[j];        // 4B-aligned only: scalar STG
                op[0] = xv[j].x + dx0;             // STE: fl(x + fl(q - x))
                op[1] = xv[j].y + dx1;
                op[2] = xv[j].z + dx2;
                op[3] = xv[j].w + dx3;
            }
        }
    }
    #pragma unroll
    for (int o = 16; o; o >>= 1) lsum += __shfl_down_sync(0xffffffffu, lsum, o);
    if ((tid & 31) == 0) ws[tid >> 5] = lsum;
    __syncthreads();
    if (tid == 0) {
        float s = 0.f;
        #pragma unroll
        for (int i = 0; i < 8; ++i) s += ws[i];
        g_bsum[blockIdx.y * 32 + blockIdx.x] = s;
    }
}

// ---------------- loss finalize --------------------------------------------
__global__ void finalize_kernel(const float* beta, float* out) {
    __shared__ float sh[256];
    int tid = threadIdx.x;
    float s = 0.f;
    for (int i = tid; i < 1024; i += 256) s += g_bsum[i];
    sh[tid] = s; __syncthreads();
    for (int o = 128; o; o >>= 1) {
        if (tid < o) sh[tid] += sh[tid + o];
        __syncthreads();
    }
    if (tid == 0) {
        float bv = 0.25f;
        if (beta) {
            float f = *beta;
            if (f > 0.0f && f < 100.0f) bv = f;
            else {
                double dv = *(const double*)beta;
                if (dv > 0.0 && dv < 100.0) bv = (float)dv;
            }
        }
        out[0] = (1.0f + bv) * (sh[0] / 33554432.0f);
    }
}

// ---------------------------------------------------------------------------
extern "C" void kernel_launch(void* const* d_in, const int* in_sizes, int n_in,
                              void* d_out, int out_size) {
    (void)in_sizes;
    const float* x    = (const float*)d_in[0];
    const float* emb  = (const float*)d_in[1];
    const float* beta = (n_in > 2) ? (const float*)d_in[2] : nullptr;
    float* out = (float*)d_out;

    int off = out_size - TENSOR_ELEMS;
    if (off < 0) off = 0;

    cudaFuncSetAttribute(argmin_kernel,
                         cudaFuncAttributeMaxDynamicSharedMemorySize, SM_TOTAL);
    cudaFuncSetAttribute(fixup_kernel,
                         cudaFuncAttributeMaxDynamicSharedMemorySize, FX_TOTAL);
    cudaFuncSetAttribute(gather_kernel,
                         cudaFuncAttributeMaxDynamicSharedMemorySize, G_TOTAL);

    prep_kernel<<<K_, 256>>>(emb);
    argmin_kernel<<<2048, 256, SM_TOTAL>>>(x);
    fixup_kernel<<<256, 256, FX_TOTAL>>>(x, emb);
    gather_kernel<<<dim3(32, 32), 256, G_TOTAL>>>(x, emb, out + off);
    if (off >= 1) finalize_kernel<<<1, 256>>>(beta, out);
}

// round 13
// speedup vs baseline: 2.9764x; 1.0361x over previous
#include <cuda_runtime.h>
#include <cuda_fp16.h>
#include <cstdint>

#define B_    32
#define D_    256
#define HW_   4096
#define K_    1024
#define NROWS (B_ * HW_)
#define TENSOR_ELEMS (B_ * D_ * HW_)
#define THRESH 1.5e-4f

__device__ __half g_eh[K_ * D_];     // fp16 of (-2*E), k-major rows
__device__ float g_enorm[K_];
__device__ int   g_idx[NROWS];
__device__ float g_bsum[1024];
__device__ int   g_fixn;
__device__ int   g_fixlist[NROWS];

// ---------------- PTX helpers (plain sm_80-level, no 'a' features) ----------
__device__ __forceinline__ uint32_t smem_u32(const void* p) {
    uint32_t a;
    asm("{ .reg .u64 t; cvta.to.shared.u64 t, %1; cvt.u32.u64 %0, t; }" : "=r"(a) : "l"(p));
    return a;
}
__device__ __forceinline__ void cp16(uint32_t dst, const void* src) {
    asm volatile("cp.async.cg.shared.global [%0], [%1], 16;" :: "r"(dst), "l"(src) : "memory");
}
#define CP_COMMIT() asm volatile("cp.async.commit_group;" ::: "memory")
#define CP_WAIT0()  asm volatile("cp.async.wait_group 0;" ::: "memory")

__device__ __forceinline__ void ldsm4(uint32_t* r, uint32_t addr) {
    asm volatile("ldmatrix.sync.aligned.m8n8.x4.shared.b16 {%0,%1,%2,%3}, [%4];"
                 : "=r"(r[0]), "=r"(r[1]), "=r"(r[2]), "=r"(r[3]) : "r"(addr));
}
__device__ __forceinline__ void mma16816(float* c, const uint32_t* a, const uint32_t* b) {
    asm volatile("mma.sync.aligned.m16n8k16.row.col.f32.f16.f16.f32 "
                 "{%0,%1,%2,%3}, {%4,%5,%6,%7}, {%8,%9}, {%0,%1,%2,%3};"
                 : "+f"(c[0]), "+f"(c[1]), "+f"(c[2]), "+f"(c[3])
                 : "r"(a[0]), "r"(a[1]), "r"(a[2]), "r"(a[3]), "r"(b[0]), "r"(b[1]));
}

// smem layout (bytes): X 32K | B 2x16K | Se 4K | red 3K  -> 71 KB, occ 3
#define SM_XHI   0
#define SM_E     32768
#define SM_SE    65536
#define SM_RED   69632
#define SM_TOTAL 72704

// ---------------- prep: fp16 of (-2E), ||e||^2 ------------------------------
__global__ void prep_kernel(const float* __restrict__ emb) {
    int k = blockIdx.x, d = threadIdx.x;
    g_eh[k * D_ + d] = __float2half(-2.0f * emb[k * D_ + d]);
    if (d == 0) {
        const float* r = emb + (size_t)k * D_;
        float s = 0.f;
        for (int i = 0; i < D_; ++i) { float v = r[i]; s = fmaf(v, v, s); }
        g_enorm[k] = s;
        if (k == 0) g_fixn = 0;
    }
}

// stage one 128-code x 64-d fp16 tile into a 16KB buffer (4 cp16/thread)
__device__ __forceinline__ void stage_B64(uint32_t ebase, const __half* Eptr, int tid) {
    #pragma unroll
    for (int i = 0; i < 4; ++i) {
        int idx = tid + i * 256;                   // 0..1023
        int r = idx >> 3, s = idx & 7;             // r: code row, s: 8-half col
        uint32_t dst = (uint32_t)((r >> 3) * 1024 + (r & 7) * 128 +
                                  ((s * 16) ^ ((r & 7) << 4)));
        cp16(ebase + dst, Eptr + (size_t)r * D_ + s * 8);
    }
    CP_COMMIT();
}

// ---------------- HMMA argmin: 64 pixels/CTA, occupancy 3 -------------------
__global__ __launch_bounds__(256, 3)
void argmin_kernel(const float* __restrict__ x) {
    extern __shared__ char smem[];
    const uint32_t sb = smem_u32(smem);
    float* sSe  = (float*)(smem + SM_SE);
    float* red  = (float*)(smem + SM_RED);

    const int tid  = threadIdx.x;
    const int lane = tid & 31;
    const int w    = tid >> 5;
    const int wm   = w & 1;        // pixel half (rows 0-31 / 32-63)
    const int wn   = w >> 1;       // code group (4 x 32 within a 128-code pass)
    const int b    = blockIdx.x >> 6;
    const int c0   = (blockIdx.x & 63) * 64;

    for (int i = tid; i < K_; i += 256) sSe[i] = g_enorm[i];

    // prefetch seg0 (pass0, chunk0) into buffer 0
    stage_B64(sb + SM_E, g_eh, tid);

    // stage X tile [64 pixels x 256 d] fp16, SW128 K-major (4 x 8KB d-chunks)
    {
        const int p = tid & 63, half = tid >> 6;   // half in 0..3: 64 d each
        const float* xb = x + (size_t)b * (D_ * HW_) + c0 + p;
        const uint32_t rowbase = (uint32_t)((p >> 3) * 1024 + (p & 7) * 128);
        const uint32_t rx = (uint32_t)((p & 7) << 4);
        for (int d0 = half * 64; d0 < half * 64 + 64; d0 += 8) {
            float v[8];
            #pragma unroll
            for (int i = 0; i < 8; ++i) v[i] = xb[(size_t)(d0 + i) * HW_];
            uint32_t hp[4];
            #pragma unroll
            for (int i = 0; i < 4; ++i) {
                __half h0 = __float2half(v[2*i]);
                __half h1 = __float2half(v[2*i+1]);
                hp[i] = (uint32_t)__half_as_ushort(h0) |
                        ((uint32_t)__half_as_ushort(h1) << 16);
            }
            uint32_t off = (uint32_t)(d0 >> 6) * 8192u + rowbase +
                           (((uint32_t)(d0 & 63) * 2u) ^ rx);
            *(uint4*)(smem + SM_XHI + off) = make_uint4(hp[0], hp[1], hp[2], hp[3]);
        }
    }

    // A-side ldmatrix constants (2 x 16x16 tiles over this warp's 32 rows)
    uint32_t aOff[2], aXor[2];
    #pragma unroll
    for (int mt = 0; mt < 2; ++mt) {
        int r = wm * 32 + mt * 16 + (lane & 7) + ((lane >> 3) & 1) * 8;
        aOff[mt] = (uint32_t)((r >> 3) * 1024 + (r & 7) * 128);
        aXor[mt] = (uint32_t)((r & 7) << 4);
    }
    const uint32_t adB = (lane >> 4) ? 16u : 0u;
    // B-side: pair two 8-col tiles per ldmatrix.x4
    uint32_t bpOff[2], bpXor[2];
    #pragma unroll
    for (int p = 0; p < 2; ++p) {
        int n = wn * 32 + p * 16 + ((lane >> 4) << 3) + (lane & 7);
        bpOff[p] = (uint32_t)((n >> 3) * 1024 + (n & 7) * 128);
        bpXor[p] = (uint32_t)((n & 7) << 4);
    }
    const uint32_t kB = (uint32_t)(((lane >> 3) & 1) << 4);

    float m1r[4], m2r[4]; int i1r[4];
    #pragma unroll
    for (int s = 0; s < 4; ++s) { m1r[s] = 3.4e38f; m2r[s] = 3.4e38f; i1r[s] = 0; }

    float acc[2][4][4];

    for (int seg = 0; seg < 32; ++seg) {        // seg = pass*4 + dchunk
        const int ch = seg & 3;
        // Hazard-safe single barrier: WAIT0 completes the group staged last
        // seg; the barrier (a) makes it visible to all warps and (b) orders
        // all of last seg's reads BEFORE this seg's cp.async overwrites.
        CP_WAIT0();
        __syncthreads();
        if (seg < 31) {
            const int ns = seg + 1;
            stage_B64(sb + SM_E + (uint32_t)(ns & 1) * 16384u,
                      g_eh + (size_t)(ns >> 2) * 128 * D_ + (ns & 3) * 64, tid);
        }

        if (ch == 0) {
            #pragma unroll
            for (int mt = 0; mt < 2; ++mt)
                #pragma unroll
                for (int nt = 0; nt < 4; ++nt)
                    #pragma unroll
                    for (int q = 0; q < 4; ++q) acc[mt][nt][q] = 0.f;
        }

        const uint32_t eh  = sb + SM_E + (uint32_t)(seg & 1) * 16384u;
        const uint32_t xco = (uint32_t)ch * 8192u;

        #pragma unroll
        for (int ks = 0; ks < 4; ++ks) {
            const uint32_t ksl = (uint32_t)ks * 32u;
            const uint32_t dA  = ksl + adB;
            uint32_t bh[4][2], ah[2][4];
            #pragma unroll
            for (int p = 0; p < 2; ++p) {
                uint32_t r4[4];
                ldsm4(r4, eh + bpOff[p] + ((ksl + kB) ^ bpXor[p]));
                bh[2*p][0] = r4[0]; bh[2*p][1] = r4[1];
                bh[2*p+1][0] = r4[2]; bh[2*p+1][1] = r4[3];
            }
            #pragma unroll
            for (int mt = 0; mt < 2; ++mt)
                ldsm4(ah[mt], sb + SM_XHI + xco + aOff[mt] + (dA ^ aXor[mt]));
            #pragma unroll
            for (int mt = 0; mt < 2; ++mt)
                #pragma unroll
                for (int nt = 0; nt < 4; ++nt)
                    mma16816(acc[mt][nt], ah[mt], bh[nt]);
        }

        if (ch == 3) {
            // fold scores: s = Se + dot (Sx dropped: rank-invariant; fixup
            // recomputes the exact reference formula for near-ties)
            const int pass = seg >> 2;
            const int cbase = pass * 128 + wn * 32 + 2 * (lane & 3);
            #pragma unroll
            for (int nt = 0; nt < 4; ++nt) {
                const int code0 = cbase + nt * 8;
                const float se0 = sSe[code0], se1 = sSe[code0 + 1];
                #pragma unroll
                for (int mt = 0; mt < 2; ++mt) {
                    const int s0 = mt * 2, s1 = mt * 2 + 1;
                    float v;
                    v = se0 + acc[mt][nt][0];
                    if (v < m1r[s0]) { m2r[s0] = m1r[s0]; m1r[s0] = v; i1r[s0] = code0; }
                    else if (v < m2r[s0]) m2r[s0] = v;
                    v = se1 + acc[mt][nt][1];
                    if (v < m1r[s0]) { m2r[s0] = m1r[s0]; m1r[s0] = v; i1r[s0] = code0 + 1; }
                    else if (v < m2r[s0]) m2r[s0] = v;
                    v = se0 + acc[mt][nt][2];
                    if (v < m1r[s1]) { m2r[s1] = m1r[s1]; m1r[s1] = v; i1r[s1] = code0; }
                    else if (v < m2r[s1]) m2r[s1] = v;
                    v = se1 + acc[mt][nt][3];
                    if (v < m1r[s1]) { m2r[s1] = m1r[s1]; m1r[s1] = v; i1r[s1] = code0 + 1; }
                    else if (v < m2r[s1]) m2r[s1] = v;
                }
            }
        }
    }

    __syncthreads();
    #pragma unroll
    for (int s = 0; s < 4; ++s) {
        float a1 = m1r[s], a2 = m2r[s]; int ai = i1r[s];
        #pragma unroll
        for (int ofs = 1; ofs <= 2; ofs <<= 1) {
            float v1 = __shfl_xor_sync(0xffffffffu, a1, ofs);
            float v2 = __shfl_xor_sync(0xffffffffu, a2, ofs);
            int   vi = __shfl_xor_sync(0xffffffffu, ai, ofs);
            if (v1 < a1 || (v1 == a1 && vi < ai)) { a2 = fminf(a1, v2); a1 = v1; ai = vi; }
            else                                  { a2 = fminf(a2, v1); }
        }
        if ((lane & 3) == 0) {
            int pix = wm * 32 + (s >> 1) * 16 + (lane >> 2) + (s & 1) * 8;
            red[(pix * 4 + wn) * 3 + 0] = a1;
            red[(pix * 4 + wn) * 3 + 1] = a2;
            red[(pix * 4 + wn) * 3 + 2] = __int_as_float(ai);
        }
    }
    __syncthreads();

    if (tid < 64) {
        float a1 = red[(tid * 4) * 3], a2 = red[(tid * 4) * 3 + 1];
        int   ai = __float_as_int(red[(tid * 4) * 3 + 2]);
        #pragma unroll
        for (int q = 1; q < 4; ++q) {
            float v1 = red[(tid * 4 + q) * 3], v2 = red[(tid * 4 + q) * 3 + 1];
            int   vi = __float_as_int(red[(tid * 4 + q) * 3 + 2]);
            if (v1 < a1 || (v1 == a1 && vi < ai)) { a2 = fminf(a1, v2); a1 = v1; ai = vi; }
            else                                  { a2 = fminf(a2, v1); }
        }
        const int row = b * HW_ + c0 + tid;
        g_idx[row] = ai;
        if (a2 - a1 < THRESH) {
            int pos = atomicAdd(&g_fixn, 1);
            g_fixlist[pos] = row;
        }
    }
}

// ---------------- exact-fp32 fixup of near-tie rows -------------------------
#define FX_SX   0
#define FX_ED   16448
#define FX_SSX  (FX_ED + 69632)
#define FX_ROWS (FX_SSX + 64)
#define FX_TOTAL (FX_ROWS + 64)

__global__ __launch_bounds__(256)
void fixup_kernel(const float* __restrict__ x, const float* __restrict__ emb) {
    extern __shared__ char fsm[];
    float* sx  = (float*)(fsm + FX_SX);    // [16][257]
    float* ed  = (float*)(fsm + FX_ED);    // [256][68]
    float* sSx = (float*)(fsm + FX_SSX);
    int*   rws = (int*)(fsm + FX_ROWS);

    const int n = g_fixn;
    const int tid = threadIdx.x;
    const int r  = tid >> 4;
    const int tc = tid & 15;

    for (int base = blockIdx.x * 16; base < n; base += gridDim.x * 16) {
        if (tid < 16) rws[tid] = (base + tid < n) ? g_fixlist[base + tid] : -1;
        __syncthreads();
        for (int i = tid; i < 16 * D_; i += 256) {
            int rr = i >> 8, d = i & 255;
            int row = rws[rr];
            int row_c = (row < 0) ? 0 : row;
            int bb = row_c >> 12, pix = row_c & 4095;
            sx[rr * 257 + d] = x[(size_t)bb * (D_ * HW_) + (size_t)d * HW_ + pix];
        }
        __syncthreads();
        if (tc == 0) {
            float s = 0.f;
            for (int d = 0; d < D_; ++d) { float v = sx[r * 257 + d]; s = fmaf(v, v, s); }
            sSx[r] = s;
        }
        float m = 3.4e38f; int bi = 0;
        for (int cb = 0; cb < 16; ++cb) {
            __syncthreads();
            {
                int cc = tid >> 2, dseg = (tid & 3) * 64;
                const float* er = emb + (size_t)(cb * 64 + cc) * D_ + dseg;
                for (int i = 0; i < 64; i += 4) {
                    float4 v = *(const float4*)(er + i);
                    ed[(dseg + i)     * 68 + cc] = v.x;
                    ed[(dseg + i + 1) * 68 + cc] = v.y;
                    ed[(dseg + i + 2) * 68 + cc] = v.z;
                    ed[(dseg + i + 3) * 68 + cc] = v.w;
                }
            }
            __syncthreads();
            float a0 = 0.f, a1 = 0.f, a2 = 0.f, a3 = 0.f;
            const float* xr = sx + r * 257;
            for (int d = 0; d < D_; ++d) {
                float xv = xr[d];
                float4 ev = *(const float4*)(ed + d * 68 + tc * 4);
                a0 = fmaf(ev.x, xv, a0);
                a1 = fmaf(ev.y, xv, a1);
                a2 = fmaf(ev.z, xv, a2);
                a3 = fmaf(ev.w, xv, a3);
            }
            float accv[4] = {a0, a1, a2, a3};
            float Sxr = sSx[r];
            #pragma unroll
            for (int j = 0; j < 4; ++j) {
                int code = cb * 64 + tc * 4 + j;
                float s = fmaf(-2.f, accv[j], Sxr + g_enorm[code]);
                if (s < m) { m = s; bi = code; }
            }
        }
        #pragma unroll
        for (int off = 8; off; off >>= 1) {
            float ov = __shfl_down_sync(0xffffffffu, m, off, 16);
            int   oi = __shfl_down_sync(0xffffffffu, bi, off, 16);
            if (ov < m || (ov == m && oi < bi)) { m = ov; bi = oi; }
        }
        if (tc == 0 && rws[r] >= 0) g_idx[rws[r]] = bi;
        __syncthreads();
    }
}

// ---------------- gather: 64-d chunks, MLP-8 batched loads, scalar stores ----
#define G_SIDX  0
#define G_WS    512
#define G_ET    1024                       // et[d][pixel], 64 x 132 floats
#define G_TOTAL (G_ET + 64 * 132 * 4)

__global__ __launch_bounds__(256)
void gather_kernel(const float* __restrict__ x, const float* __restrict__ emb,
                   float* __restrict__ outT) {
    extern __shared__ char gsm[];
    int*   sidx = (int*)(gsm + G_SIDX);
    float* ws   = (float*)(gsm + G_WS);
    float* et   = (float*)(gsm + G_ET);

    const int tid = threadIdx.x;
    const int b   = blockIdx.y;
    const int c0  = blockIdx.x * 128;
    if (tid < 128) sidx[tid] = g_idx[b * HW_ + c0 + tid];
    __syncthreads();

    const int pg = (tid & 31) * 4;     // 4-pixel group within warp
    const int dg = tid >> 5;           // warp -> 8 d rows per 64-d chunk
    float lsum = 0.f;

    for (int d0 = 0; d0 < D_; d0 += 64) {
        if (d0) __syncthreads();
        #pragma unroll
        for (int i = 0; i < 8; ++i) {
            int idx = tid + i * 256;
            int p = idx & 127, f4 = idx >> 7;
            float4 v = *(const float4*)(emb + (size_t)sidx[p] * D_ + d0 + f4 * 4);
            et[(f4 * 4 + 0) * 132 + p] = v.x;
            et[(f4 * 4 + 1) * 132 + p] = v.y;
            et[(f4 * 4 + 2) * 132 + p] = v.z;
            et[(f4 * 4 + 3) * 132 + p] = v.w;
        }
        __syncthreads();
        // batch ALL 8 x loads first (MLP=8), then compute + scalar stores
        const size_t base0 = (size_t)b * (D_ * HW_) + (size_t)(d0 + dg * 8) * HW_ + c0 + pg;
        float4 xv[8];
        #pragma unroll
        for (int j = 0; j < 8; ++j)
            xv[j] = *(const float4*)(x + base0 + (size_t)j * HW_);
        #pragma unroll
        for (int j = 0; j < 8; ++j) {
            float4 q = *(const float4*)(et + (dg * 8 + j) * 132 + pg);
            float dx0 = q.x - xv[j].x, dx1 = q.y - xv[j].y;
            float dx2 = q.z - xv[j].z, dx3 = q.w - xv[j].w;
            lsum = fmaf(dx0, dx0, lsum); lsum = fmaf(dx1, dx1, lsum);
            lsum = fmaf(dx2, dx2, lsum); lsum = fmaf(dx3, dx3, lsum);
            float* op = outT + base0 + (size_t)j * HW_;   // 4B-aligned: scalar STG
            op[0] = xv[j].x + dx0;                        // STE: fl(x + fl(q - x))
            op[1] = xv[j].y + dx1;
            op[2] = xv[j].z + dx2;
            op[3] = xv[j].w + dx3;
        }
    }
    #pragma unroll
    for (int o = 16; o; o >>= 1) lsum += __shfl_down_sync(0xffffffffu, lsum, o);
    if ((tid & 31) == 0) ws[tid >> 5] = lsum;
    __syncthreads();
    if (tid == 0) {
        float s = 0.f;
        #pragma unroll
        for (int i = 0; i < 8; ++i) s += ws[i];
        g_bsum[blockIdx.y * 32 + blockIdx.x] = s;
    }
}

// ---------------- loss finalize --------------------------------------------
__global__ void finalize_kernel(const float* beta, float* out) {
    __shared__ float sh[256];
    int tid = threadIdx.x;
    float s = 0.f;
    for (int i = tid; i < 1024; i += 256) s += g_bsum[i];
    sh[tid] = s; __syncthreads();
    for (int o = 128; o; o >>= 1) {
        if (tid < o) sh[tid] += sh[tid + o];
        __syncthreads();
    }
    if (tid == 0) {
        float bv = 0.25f;
        if (beta) {
            float f = *beta;
            if (f > 0.0f && f < 100.0f) bv = f;
            else {
                double dv = *(const double*)beta;
                if (dv > 0.0 && dv < 100.0) bv = (float)dv;
            }
        }
        out[0] = (1.0f + bv) * (sh[0] / 33554432.0f);
    }
}

// ---------------------------------------------------------------------------
extern "C" void kernel_launch(void* const* d_in, const int* in_sizes, int n_in,
                              void* d_out, int out_size) {
    (void)in_sizes;
    const float* x    = (const float*)d_in[0];
    const float* emb  = (const float*)d_in[1];
    const float* beta = (n_in > 2) ? (const float*)d_in[2] : nullptr;
    float* out = (float*)d_out;

    int off = out_size - TENSOR_ELEMS;
    if (off < 0) off = 0;

    cudaFuncSetAttribute(argmin_kernel,
                         cudaFuncAttributeMaxDynamicSharedMemorySize, SM_TOTAL);
    cudaFuncSetAttribute(fixup_kernel,
                         cudaFuncAttributeMaxDynamicSharedMemorySize, FX_TOTAL);
    cudaFuncSetAttribute(gather_kernel,
                         cudaFuncAttributeMaxDynamicSharedMemorySize, G_TOTAL);

    prep_kernel<<<K_, 256>>>(emb);
    argmin_kernel<<<2048, 256, SM_TOTAL>>>(x);
    fixup_kernel<<<256, 256, FX_TOTAL>>>(x, emb);
    gather_kernel<<<dim3(32, 32), 256, G_TOTAL>>>(x, emb, out + off);
    if (off >= 1) finalize_kernel<<<1, 256>>>(beta, out);
}

// round 14
// speedup vs baseline: 2.9798x; 1.0012x over previous
#include <cuda_runtime.h>
#include <cuda_fp16.h>
#include <cstdint>

#define B_    32
#define D_    256
#define HW_   4096
#define K_    1024
#define NROWS (B_ * HW_)
#define TENSOR_ELEMS (B_ * D_ * HW_)
#define THRESH 1.5e-4f

__device__ __half g_eh[K_ * D_];     // fp16 of (-2*E), k-major rows
__device__ float g_enorm[K_];
__device__ int   g_idx[NROWS];
__device__ float g_bsum[1024];
__device__ int   g_fixn;
__device__ int   g_fixlist[NROWS];

// ---------------- PTX helpers (plain sm_80-level, no 'a' features) ----------
__device__ __forceinline__ uint32_t smem_u32(const void* p) {
    uint32_t a;
    asm("{ .reg .u64 t; cvta.to.shared.u64 t, %1; cvt.u32.u64 %0, t; }" : "=r"(a) : "l"(p));
    return a;
}
__device__ __forceinline__ void cp16(uint32_t dst, const void* src) {
    asm volatile("cp.async.cg.shared.global [%0], [%1], 16;" :: "r"(dst), "l"(src) : "memory");
}
#define CP_COMMIT() asm volatile("cp.async.commit_group;" ::: "memory")
#define CP_WAIT0()  asm volatile("cp.async.wait_group 0;" ::: "memory")

__device__ __forceinline__ void ldsm4(uint32_t* r, uint32_t addr) {
    asm volatile("ldmatrix.sync.aligned.m8n8.x4.shared.b16 {%0,%1,%2,%3}, [%4];"
                 : "=r"(r[0]), "=r"(r[1]), "=r"(r[2]), "=r"(r[3]) : "r"(addr));
}
__device__ __forceinline__ void mma16816(float* c, const uint32_t* a, const uint32_t* b) {
    asm volatile("mma.sync.aligned.m16n8k16.row.col.f32.f16.f16.f32 "
                 "{%0,%1,%2,%3}, {%4,%5,%6,%7}, {%8,%9}, {%0,%1,%2,%3};"
                 : "+f"(c[0]), "+f"(c[1]), "+f"(c[2]), "+f"(c[3])
                 : "r"(a[0]), "r"(a[1]), "r"(a[2]), "r"(a[3]), "r"(b[0]), "r"(b[1]));
}

// smem layout (bytes): X 32K | B 2x32K | Se 4K | red 3K  -> 103 KB, occ 2
#define SM_XHI   0
#define SM_E     32768
#define SM_SE    98304
#define SM_RED   102400
#define SM_TOTAL 105472

// ---------------- dummy: shifts argmin into ncu's capture window ------------
__global__ void dummy_kernel() {
    if (blockIdx.x > 1000) g_bsum[0] = 0.f;   // never true (grid = 1)
}

// ---------------- prep: fp16 of (-2E), ||e||^2 ------------------------------
__global__ void prep_kernel(const float* __restrict__ emb) {
    int k = blockIdx.x, d = threadIdx.x;
    g_eh[k * D_ + d] = __float2half(-2.0f * emb[k * D_ + d]);
    if (d == 0) {
        const float* r = emb + (size_t)k * D_;
        float s = 0.f;
        for (int i = 0; i < D_; ++i) { float v = r[i]; s = fmaf(v, v, s); }
        g_enorm[k] = s;
        if (k == 0) g_fixn = 0;
    }
}

// stage one 256-code x 64-d fp16 tile into a 32KB buffer (8 cp16/thread)
__device__ __forceinline__ void stage_B256(uint32_t ebase, const __half* Eptr, int tid) {
    #pragma unroll
    for (int i = 0; i < 8; ++i) {
        int idx = tid + i * 256;                   // 0..2047
        int r = idx >> 3, s = idx & 7;             // r: code row 0..255, s: 8-half col
        uint32_t dst = (uint32_t)((r >> 3) * 1024 + (r & 7) * 128 +
                                  ((s * 16) ^ ((r & 7) << 4)));
        cp16(ebase + dst, Eptr + (size_t)r * D_ + s * 8);
    }
    CP_COMMIT();
}

// ---------------- HMMA argmin: 64 pixels/CTA, warp tile 32x64, occ 2 --------
__global__ __launch_bounds__(256, 2)
void argmin_kernel(const float* __restrict__ x) {
    extern __shared__ char smem[];
    const uint32_t sb = smem_u32(smem);
    float* sSe  = (float*)(smem + SM_SE);
    float* red  = (float*)(smem + SM_RED);

    const int tid  = threadIdx.x;
    const int lane = tid & 31;
    const int w    = tid >> 5;
    const int wm   = w & 1;        // pixel half (rows 0-31 / 32-63)
    const int wn   = w >> 1;       // code group (4 x 64 within a 256-code pass)
    const int b    = blockIdx.x >> 6;
    const int c0   = (blockIdx.x & 63) * 64;

    for (int i = tid; i < K_; i += 256) sSe[i] = g_enorm[i];

    // prefetch seg0 (pass0, dchunk0) into buffer 0
    stage_B256(sb + SM_E, g_eh, tid);

    // stage X tile [64 pixels x 256 d] fp16, SW128 K-major (4 x 8KB d-chunks)
    {
        const int p = tid & 63, half = tid >> 6;   // half in 0..3: 64 d each
        const float* xb = x + (size_t)b * (D_ * HW_) + c0 + p;
        const uint32_t rowbase = (uint32_t)((p >> 3) * 1024 + (p & 7) * 128);
        const uint32_t rx = (uint32_t)((p & 7) << 4);
        for (int d0 = half * 64; d0 < half * 64 + 64; d0 += 8) {
            float v[8];
            #pragma unroll
            for (int i = 0; i < 8; ++i) v[i] = xb[(size_t)(d0 + i) * HW_];
            uint32_t hp[4];
            #pragma unroll
            for (int i = 0; i < 4; ++i) {
                __half h0 = __float2half(v[2*i]);
                __half h1 = __float2half(v[2*i+1]);
                hp[i] = (uint32_t)__half_as_ushort(h0) |
                        ((uint32_t)__half_as_ushort(h1) << 16);
            }
            uint32_t off = (uint32_t)(d0 >> 6) * 8192u + rowbase +
                           (((uint32_t)(d0 & 63) * 2u) ^ rx);
            *(uint4*)(smem + SM_XHI + off) = make_uint4(hp[0], hp[1], hp[2], hp[3]);
        }
    }

    // A-side ldmatrix constants (2 x 16x16 tiles over this warp's 32 rows)
    uint32_t aOff[2], aXor[2];
    #pragma unroll
    for (int mt = 0; mt < 2; ++mt) {
        int r = wm * 32 + mt * 16 + (lane & 7) + ((lane >> 3) & 1) * 8;
        aOff[mt] = (uint32_t)((r >> 3) * 1024 + (r & 7) * 128);
        aXor[mt] = (uint32_t)((r & 7) << 4);
    }
    const uint32_t adB = (lane >> 4) ? 16u : 0u;
    // B-side: 4 paired ldsm4 -> 8 n-tiles of 8 codes (warp covers 64 codes)
    uint32_t bpOff[4], bpXor[4];
    #pragma unroll
    for (int p = 0; p < 4; ++p) {
        int n = wn * 64 + p * 16 + ((lane >> 4) << 3) + (lane & 7);
        bpOff[p] = (uint32_t)((n >> 3) * 1024 + (n & 7) * 128);
        bpXor[p] = (uint32_t)((n & 7) << 4);
    }
    const uint32_t kB = (uint32_t)(((lane >> 3) & 1) << 4);

    float m1r[4], m2r[4]; int i1r[4];
    #pragma unroll
    for (int s = 0; s < 4; ++s) { m1r[s] = 3.4e38f; m2r[s] = 3.4e38f; i1r[s] = 0; }

    float acc[2][8][4];

    for (int seg = 0; seg < 16; ++seg) {        // seg = pass*4 + dchunk
        const int ch = seg & 3;
        // Hazard-safe single barrier: WAIT0 completes the group staged last
        // seg; the barrier (a) makes it visible to all warps and (b) orders
        // all of last seg's reads BEFORE this seg's cp.async overwrites.
        CP_WAIT0();
        __syncthreads();
        if (seg < 15) {
            const int ns = seg + 1;
            stage_B256(sb + SM_E + (uint32_t)(ns & 1) * 32768u,
                       g_eh + (size_t)(ns >> 2) * 256 * D_ + (ns & 3) * 64, tid);
        }

        if (ch == 0) {
            #pragma unroll
            for (int mt = 0; mt < 2; ++mt)
                #pragma unroll
                for (int nt = 0; nt < 8; ++nt)
                    #pragma unroll
                    for (int q = 0; q < 4; ++q) acc[mt][nt][q] = 0.f;
        }

        const uint32_t eh  = sb + SM_E + (uint32_t)(seg & 1) * 32768u;
        const uint32_t xco = (uint32_t)ch * 8192u;

        #pragma unroll
        for (int ks = 0; ks < 4; ++ks) {
            const uint32_t ksl = (uint32_t)ks * 32u;
            const uint32_t dA  = ksl + adB;
            uint32_t bh[8][2], ah[2][4];
            #pragma unroll
            for (int p = 0; p < 4; ++p) {
                uint32_t r4[4];
                ldsm4(r4, eh + bpOff[p] + ((ksl + kB) ^ bpXor[p]));
                bh[2*p][0] = r4[0]; bh[2*p][1] = r4[1];
                bh[2*p+1][0] = r4[2]; bh[2*p+1][1] = r4[3];
            }
            #pragma unroll
            for (int mt = 0; mt < 2; ++mt)
                ldsm4(ah[mt], sb + SM_XHI + xco + aOff[mt] + (dA ^ aXor[mt]));
            #pragma unroll
            for (int mt = 0; mt < 2; ++mt)
                #pragma unroll
                for (int nt = 0; nt < 8; ++nt)
                    mma16816(acc[mt][nt], ah[mt], bh[nt]);
        }

        if (ch == 3) {
            // fold scores: s = Se + dot (Sx dropped: rank-invariant; fixup
            // recomputes the exact reference formula for near-ties)
            const int pass = seg >> 2;
            const int cbase = pass * 256 + wn * 64 + 2 * (lane & 3);
            #pragma unroll
            for (int nt = 0; nt < 8; ++nt) {
                const int code0 = cbase + nt * 8;
                const float se0 = sSe[code0], se1 = sSe[code0 + 1];
                #pragma unroll
                for (int mt = 0; mt < 2; ++mt) {
                    const int s0 = mt * 2, s1 = mt * 2 + 1;
                    float v;
                    v = se0 + acc[mt][nt][0];
                    if (v < m1r[s0]) { m2r[s0] = m1r[s0]; m1r[s0] = v; i1r[s0] = code0; }
                    else if (v < m2r[s0]) m2r[s0] = v;
                    v = se1 + acc[mt][nt][1];
                    if (v < m1r[s0]) { m2r[s0] = m1r[s0]; m1r[s0] = v; i1r[s0] = code0 + 1; }
                    else if (v < m2r[s0]) m2r[s0] = v;
                    v = se0 + acc[mt][nt][2];
                    if (v < m1r[s1]) { m2r[s1] = m1r[s1]; m1r[s1] = v; i1r[s1] = code0; }
                    else if (v < m2r[s1]) m2r[s1] = v;
                    v = se1 + acc[mt][nt][3];
                    if (v < m1r[s1]) { m2r[s1] = m1r[s1]; m1r[s1] = v; i1r[s1] = code0 + 1; }
                    else if (v < m2r[s1]) m2r[s1] = v;
                }
            }
        }
    }

    __syncthreads();
    #pragma unroll
    for (int s = 0; s < 4; ++s) {
        float a1 = m1r[s], a2 = m2r[s]; int ai = i1r[s];
        #pragma unroll
        for (int ofs = 1; ofs <= 2; ofs <<= 1) {
            float v1 = __shfl_xor_sync(0xffffffffu, a1, ofs);
            float v2 = __shfl_xor_sync(0xffffffffu, a2, ofs);
            int   vi = __shfl_xor_sync(0xffffffffu, ai, ofs);
            if (v1 < a1 || (v1 == a1 && vi < ai)) { a2 = fminf(a1, v2); a1 = v1; ai = vi; }
            else                                  { a2 = fminf(a2, v1); }
        }
        if ((lane & 3) == 0) {
            int pix = wm * 32 + (s >> 1) * 16 + (lane >> 2) + (s & 1) * 8;
            red[(pix * 4 + wn) * 3 + 0] = a1;
            red[(pix * 4 + wn) * 3 + 1] = a2;
            red[(pix * 4 + wn) * 3 + 2] = __int_as_float(ai);
        }
    }
    __syncthreads();

    if (tid < 64) {
        float a1 = red[(tid * 4) * 3], a2 = red[(tid * 4) * 3 + 1];
        int   ai = __float_as_int(red[(tid * 4) * 3 + 2]);
        #pragma unroll
        for (int q = 1; q < 4; ++q) {
            float v1 = red[(tid * 4 + q) * 3], v2 = red[(tid * 4 + q) * 3 + 1];
            int   vi = __float_as_int(red[(tid * 4 + q) * 3 + 2]);
            if (v1 < a1 || (v1 == a1 && vi < ai)) { a2 = fminf(a1, v2); a1 = v1; ai = vi; }
            else                                  { a2 = fminf(a2, v1); }
        }
        const int row = b * HW_ + c0 + tid;
        g_idx[row] = ai;
        if (a2 - a1 < THRESH) {
            int pos = atomicAdd(&g_fixn, 1);
            g_fixlist[pos] = row;
        }
    }
}

// ---------------- exact-fp32 fixup of near-tie rows -------------------------
#define FX_SX   0
#define FX_ED   16448
#define FX_SSX  (FX_ED + 69632)
#define FX_ROWS (FX_SSX + 64)
#define FX_TOTAL (FX_ROWS + 64)

__global__ __launch_bounds__(256)
void fixup_kernel(const float* __restrict__ x, const float* __restrict__ emb) {
    extern __shared__ char fsm[];
    float* sx  = (float*)(fsm + FX_SX);    // [16][257]
    float* ed  = (float*)(fsm + FX_ED);    // [256][68]
    float* sSx = (float*)(fsm + FX_SSX);
    int*   rws = (int*)(fsm + FX_ROWS);

    const int n = g_fixn;
    const int tid = threadIdx.x;
    const int r  = tid >> 4;
    const int tc = tid & 15;

    for (int base = blockIdx.x * 16; base < n; base += gridDim.x * 16) {
        if (tid < 16) rws[tid] = (base + tid < n) ? g_fixlist[base + tid] : -1;
        __syncthreads();
        for (int i = tid; i < 16 * D_; i += 256) {
            int rr = i >> 8, d = i & 255;
            int row = rws[rr];
            int row_c = (row < 0) ? 0 : row;
            int bb = row_c >> 12, pix = row_c & 4095;
            sx[rr * 257 + d] = x[(size_t)bb * (D_ * HW_) + (size_t)d * HW_ + pix];
        }
        __syncthreads();
        if (tc == 0) {
            float s = 0.f;
            for (int d = 0; d < D_; ++d) { float v = sx[r * 257 + d]; s = fmaf(v, v, s); }
            sSx[r] = s;
        }
        float m = 3.4e38f; int bi = 0;
        for (int cb = 0; cb < 16; ++cb) {
            __syncthreads();
            {
                int cc = tid >> 2, dseg = (tid & 3) * 64;
                const float* er = emb + (size_t)(cb * 64 + cc) * D_ + dseg;
                for (int i = 0; i < 64; i += 4) {
                    float4 v = *(const float4*)(er + i);
                    ed[(dseg + i)     * 68 + cc] = v.x;
                    ed[(dseg + i + 1) * 68 + cc] = v.y;
                    ed[(dseg + i + 2) * 68 + cc] = v.z;
                    ed[(dseg + i + 3) * 68 + cc] = v.w;
                }
            }
            __syncthreads();
            float a0 = 0.f, a1 = 0.f, a2 = 0.f, a3 = 0.f;
            const float* xr = sx + r * 257;
            for (int d = 0; d < D_; ++d) {
                float xv = xr[d];
                float4 ev = *(const float4*)(ed + d * 68 + tc * 4);
                a0 = fmaf(ev.x, xv, a0);
                a1 = fmaf(ev.y, xv, a1);
                a2 = fmaf(ev.z, xv, a2);
                a3 = fmaf(ev.w, xv, a3);
            }
            float accv[4] = {a0, a1, a2, a3};
            float Sxr = sSx[r];
            #pragma unroll
            for (int j = 0; j < 4; ++j) {
                int code = cb * 64 + tc * 4 + j;
                float s = fmaf(-2.f, accv[j], Sxr + g_enorm[code]);
                if (s < m) { m = s; bi = code; }
            }
        }
        #pragma unroll
        for (int off = 8; off; off >>= 1) {
            float ov = __shfl_down_sync(0xffffffffu, m, off, 16);
            int   oi = __shfl_down_sync(0xffffffffu, bi, off, 16);
            if (ov < m || (ov == m && oi < bi)) { m = ov; bi = oi; }
        }
        if (tc == 0 && rws[r] >= 0) g_idx[rws[r]] = bi;
        __syncthreads();
    }
}

// ---------------- gather: 64-d chunks, MLP-8 batched loads, scalar stores ----
#define G_SIDX  0
#define G_WS    512
#define G_ET    1024                       // et[d][pixel], 64 x 132 floats
#define G_TOTAL (G_ET + 64 * 132 * 4)

__global__ __launch_bounds__(256)
void gather_kernel(const float* __restrict__ x, const float* __restrict__ emb,
                   float* __restrict__ outT) {
    extern __shared__ char gsm[];
    int*   sidx = (int*)(gsm + G_SIDX);
    float* ws   = (float*)(gsm + G_WS);
    float* et   = (float*)(gsm + G_ET);

    const int tid = threadIdx.x;
    const int b   = blockIdx.y;
    const int c0  = blockIdx.x * 128;
    if (tid < 128) sidx[tid] = g_idx[b * HW_ + c0 + tid];
    __syncthreads();

    const int pg = (tid & 31) * 4;     // 4-pixel group within warp
    const int dg = tid >> 5;           // warp -> 8 d rows per 64-d chunk
    float lsum = 0.f;

    for (int d0 = 0; d0 < D_; d0 += 64) {
        if (d0) __syncthreads();
        #pragma unroll
        for (int i = 0; i < 8; ++i) {
            int idx = tid + i * 256;
            int p = idx & 127, f4 = idx >> 7;
            float4 v = *(const float4*)(emb + (size_t)sidx[p] * D_ + d0 + f4 * 4);
            et[(f4 * 4 + 0) * 132 + p] = v.x;
            et[(f4 * 4 + 1) * 132 + p] = v.y;
            et[(f4 * 4 + 2) * 132 + p] = v.z;
            et[(f4 * 4 + 3) * 132 + p] = v.w;
        }
        __syncthreads();
        // batch ALL 8 x loads first (MLP=8), then compute + scalar stores
        const size_t base0 = (size_t)b * (D_ * HW_) + (size_t)(d0 + dg * 8) * HW_ + c0 + pg;
        float4 xv[8];
        #pragma unroll
        for (int j = 0; j < 8; ++j)
            xv[j] = *(const float4*)(x + base0 + (size_t)j * HW_);
        #pragma unroll
        for (int j = 0; j < 8; ++j) {
            float4 q = *(const float4*)(et + (dg * 8 + j) * 132 + pg);
            float dx0 = q.x - xv[j].x, dx1 = q.y - xv[j].y;
            float dx2 = q.z - xv[j].z, dx3 = q.w - xv[j].w;
            lsum = fmaf(dx0, dx0, lsum); lsum = fmaf(dx1, dx1, lsum);
            lsum = fmaf(dx2, dx2, lsum); lsum = fmaf(dx3, dx3, lsum);
            float* op = outT + base0 + (size_t)j * HW_;   // 4B-aligned: scalar STG
            op[0] = xv[j].x + dx0;                        // STE: fl(x + fl(q - x))
            op[1] = xv[j].y + dx1;
            op[2] = xv[j].z + dx2;
            op[3] = xv[j].w + dx3;
        }
    }
    #pragma unroll
    for (int o = 16; o; o >>= 1) lsum += __shfl_down_sync(0xffffffffu, lsum, o);
    if ((tid & 31) == 0) ws[tid >> 5] = lsum;
    __syncthreads();
    if (tid == 0) {
        float s = 0.f;
        #pragma unroll
        for (int i = 0; i < 8; ++i) s += ws[i];
        g_bsum[blockIdx.y * 32 + blockIdx.x] = s;
    }
}

// ---------------- loss finalize --------------------------------------------
__global__ void finalize_kernel(const float* beta, float* out) {
    __shared__ float sh[256];
    int tid = threadIdx.x;
    float s = 0.f;
    for (int i = tid; i < 1024; i += 256) s += g_bsum[i];
    sh[tid] = s; __syncthreads();
    for (int o = 128; o; o >>= 1) {
        if (tid < o) sh[tid] += sh[tid + o];
        __syncthreads();
    }
    if (tid == 0) {
        float bv = 0.25f;
        if (beta) {
            float f = *beta;
            if (f > 0.0f && f < 100.0f) bv = f;
            else {
                double dv = *(const double*)beta;
                if (dv > 0.0 && dv < 100.0) bv = (float)dv;
            }
        }
        out[0] = (1.0f + bv) * (sh[0] / 33554432.0f);
    }
}

// ---------------------------------------------------------------------------
extern "C" void kernel_launch(void* const* d_in, const int* in_sizes, int n_in,
                              void* d_out, int out_size) {
    (void)in_sizes;
    const float* x    = (const float*)d_in[0];
    const float* emb  = (const float*)d_in[1];
    const float* beta = (n_in > 2) ? (const float*)d_in[2] : nullptr;
    float* out = (float*)d_out;

    int off = out_size - TENSOR_ELEMS;
    if (off < 0) off = 0;

    cudaFuncSetAttribute(argmin_kernel,
                         cudaFuncAttributeMaxDynamicSharedMemorySize, SM_TOTAL);
    cudaFuncSetAttribute(fixup_kernel,
                         cudaFuncAttributeMaxDynamicSharedMemorySize, FX_TOTAL);
    cudaFuncSetAttribute(gather_kernel,
                         cudaFuncAttributeMaxDynamicSharedMemorySize, G_TOTAL);

    prep_kernel<<<K_, 256>>>(emb);
    dummy_kernel<<<1, 32>>>();              // shift argmin into ncu's window
    dummy_kernel<<<1, 32>>>();
    argmin_kernel<<<2048, 256, SM_TOTAL>>>(x);
    fixup_kernel<<<256, 256, FX_TOTAL>>>(x, emb);
    gather_kernel<<<dim3(32, 32), 256, G_TOTAL>>>(x, emb, out + off);
    if (off >= 1) finalize_kernel<<<1, 256>>>(beta, out);
}